// round 2
// baseline (speedup 1.0000x reference)
#include <cuda_runtime.h>

// Problem dims (fixed by the dataset)
#define Vv 32000
#define Ee 1024
#define Hh 1024
#define Ll 2
#define Bb 64
#define Tt 512
#define G3 (3*Hh)

// Output packing: (out [1,B,H]) (hidden [L,B,H]) (hiddens [B,T,H])
#define OUT_OFF  0
#define HID_OFF  (Bb*Hh)
#define HIDS_OFF (Bb*Hh + Ll*Bb*Hh)

// Persistent recurrence partitioning
#define RGRID 128         // 16 n-tiles x 8 k-splits; 1 block/SM -> co-resident on 148 SMs
#define RNT   16          // n tiles
#define RTN   192         // cols per n tile (16*192 = 3072)
#define RKT   8           // k splits
#define RKC   128         // k per split (8*128 = 1024)

// Scratch (device globals: allocation-free per harness rules)
__device__ float g_xs[(size_t)Tt * Bb * Ee];       // embedded input, row = t*B+b
__device__ float g_states[(size_t)Tt * Bb * Hh];   // layer-0 states, row = t*B+b
__device__ float g_gx[(size_t)Tt * Bb * G3];       // input-side gate preacts (per layer, reused)
__device__ float g_part[(size_t)RKT * Bb * G3];    // recurrent GEMM k-split partials
__device__ float g_h[Ll * Bb * Hh];                // running hidden state per layer

// Grid barrier state (sense-reversing, self-resetting)
__device__ unsigned g_bar_arrive = 0;
__device__ unsigned g_bar_release = 0;

// ---------------------------------------------------------------------------
// f32x2 packed helpers (B300: FFMA-3reg is half rate; fma.rn.f32x2 is full)
// ---------------------------------------------------------------------------
__device__ __forceinline__ unsigned long long pk2(float x) {
    unsigned long long d;
    asm("mov.b64 %0, {%1, %1};" : "=l"(d) : "r"(__float_as_uint(x)));
    return d;
}
__device__ __forceinline__ void fma2(unsigned long long& c, unsigned long long a,
                                     unsigned long long b) {
    asm("fma.rn.f32x2 %0, %1, %2, %0;" : "+l"(c) : "l"(a), "l"(b));
}
__device__ __forceinline__ float2 upk2(unsigned long long d) {
    unsigned lo, hi;
    asm("mov.b64 {%0, %1}, %2;" : "=r"(lo), "=r"(hi) : "l"(d));
    return make_float2(__uint_as_float(lo), __uint_as_float(hi));
}

__device__ __forceinline__ void grid_bar() {
    __syncthreads();
    if (threadIdx.x == 0) {
        __threadfence();
        unsigned gen = *(volatile unsigned*)&g_bar_release;
        unsigned a = atomicAdd(&g_bar_arrive, 1u);
        if (a == RGRID - 1) {
            g_bar_arrive = 0;
            __threadfence();
            atomicAdd(&g_bar_release, 1u);
        } else {
            while (*(volatile unsigned*)&g_bar_release == gen) { __nanosleep(64); }
        }
        __threadfence();
    }
    __syncthreads();
}

// ---------------------------------------------------------------------------
// Embedding gather: xs[t*B+b, :] = embedding[x[b,t], :]
// ---------------------------------------------------------------------------
__global__ void embed_kernel(const int* __restrict__ x, const float* __restrict__ emb) {
    int row = blockIdx.x;          // t*B + b
    int t = row / Bb;
    int b = row - t * Bb;
    int tok = x[b * Tt + t];
    const float4* src = reinterpret_cast<const float4*>(emb + (size_t)tok * Ee);
    float4* dst = reinterpret_cast<float4*>(g_xs + (size_t)row * Ee);
    dst[threadIdx.x] = src[threadIdx.x];
}

__global__ void init_h(const float* __restrict__ h0) {
    int i = blockIdx.x * blockDim.x + threadIdx.x;
    if (i < Ll * Bb * Hh) g_h[i] = h0[i];
}

// ---------------------------------------------------------------------------
// Big input-side GEMM: g_gx[m, n] = sum_k A[m,k] * W[n,k] + bias[n]
//   A = g_xs (layer 0) or g_states (layer 1); M = T*B = 32768, N = 3072, K = 1024
// (verbatim from round-1: ran correctly)
// ---------------------------------------------------------------------------
#define GBM 128
#define GBN 128
#define GBK 16

__global__ __launch_bounds__(256) void sgemm_gx(int src_states,
                                                const float* __restrict__ W,
                                                const float* __restrict__ bias) {
    __shared__ float As[GBK][GBM + 4];
    __shared__ float Bs[GBK][GBN + 4];

    const float* A = src_states ? g_states : g_xs;
    const int K = 1024;
    int m0 = blockIdx.y * GBM;
    int n0 = blockIdx.x * GBN;
    int tid = threadIdx.x;
    int tm = tid >> 4;
    int tn = tid & 15;

    float acc[8][8];
#pragma unroll
    for (int i = 0; i < 8; i++)
#pragma unroll
        for (int j = 0; j < 8; j++) acc[i][j] = 0.f;

    for (int kt = 0; kt < K; kt += GBK) {
#pragma unroll
        for (int i = 0; i < 2; i++) {
            int f = tid + i * 256;
            int r = f >> 2;
            int kc = (f & 3) * 4;
            float4 va = *reinterpret_cast<const float4*>(&A[(size_t)(m0 + r) * K + kt + kc]);
            As[kc + 0][r] = va.x; As[kc + 1][r] = va.y;
            As[kc + 2][r] = va.z; As[kc + 3][r] = va.w;
            float4 vb = *reinterpret_cast<const float4*>(&W[(size_t)(n0 + r) * K + kt + kc]);
            Bs[kc + 0][r] = vb.x; Bs[kc + 1][r] = vb.y;
            Bs[kc + 2][r] = vb.z; Bs[kc + 3][r] = vb.w;
        }
        __syncthreads();

#pragma unroll
        for (int k = 0; k < GBK; k++) {
            float a[8], b[8];
            *reinterpret_cast<float4*>(&a[0]) = *reinterpret_cast<float4*>(&As[k][tm * 8]);
            *reinterpret_cast<float4*>(&a[4]) = *reinterpret_cast<float4*>(&As[k][tm * 8 + 4]);
            *reinterpret_cast<float4*>(&b[0]) = *reinterpret_cast<float4*>(&Bs[k][tn * 8]);
            *reinterpret_cast<float4*>(&b[4]) = *reinterpret_cast<float4*>(&Bs[k][tn * 8 + 4]);
#pragma unroll
            for (int i = 0; i < 8; i++)
#pragma unroll
                for (int j = 0; j < 8; j++) acc[i][j] += a[i] * b[j];
        }
        __syncthreads();
    }

#pragma unroll
    for (int i = 0; i < 8; i++) {
        size_t crow = (size_t)(m0 + tm * 8 + i) * G3;
#pragma unroll
        for (int j = 0; j < 8; j++) {
            int col = n0 + tn * 8 + j;
            g_gx[crow + col] = acc[i][j] + bias[col];
        }
    }
}

// ---------------------------------------------------------------------------
// Persistent recurrence kernel: one launch runs all 512 steps of one layer.
// Block = (kt, nt): kt = bid>>4 (K-split of 128), nt = bid&15 (192-col tile).
// Smem: W slice [128k][192n] (96KB, loaded once) + h chunk [128k][64b] (32KB).
// Per step: stage h chunk -> f32x2 microtile GEMM -> partials -> grid barrier
//           -> fused 8-way reduce + gates + state update -> grid barrier.
// ---------------------------------------------------------------------------
extern __shared__ float s_dyn[];

__global__ __launch_bounds__(256, 1) void gru_layer_persist(
    int l, const float* __restrict__ Whh_all, const float* __restrict__ bhh_all,
    float* __restrict__ dout) {

    float* Ws = s_dyn;                 // [RKC][RTN] = 128*192 floats
    float* Hs = s_dyn + RKC * RTN;     // [RKC][64]  = 128*64 floats

    const int tid = threadIdx.x;
    const int bid = blockIdx.x;
    const int nt = bid & 15;
    const int kt = bid >> 4;
    const int n0g = nt * RTN;          // global col base of this tile
    const int k0 = kt * RKC;           // global k base of this slice

    const float* W = Whh_all + (size_t)l * G3 * Hh;
    const float* bhh = bhh_all + l * G3;
    const float* hbase = g_h + l * Bb * Hh;

    // Load W slice once: rows n0g..+192, cols k0..+128. Lanes vary over r so
    // the STS is conflict-free (startup-only; uncoalesced LDG is fine here).
    for (int f = tid; f < RTN * (RKC / 4); f += 256) {
        int kc4 = f / RTN;             // 0..31
        int r = f - kc4 * RTN;         // 0..191
        float4 v = *reinterpret_cast<const float4*>(&W[(size_t)(n0g + r) * Hh + k0 + kc4 * 4]);
        Ws[(kc4 * 4 + 0) * RTN + r] = v.x;
        Ws[(kc4 * 4 + 1) * RTN + r] = v.y;
        Ws[(kc4 * 4 + 2) * RTN + r] = v.z;
        Ws[(kc4 * 4 + 3) * RTN + r] = v.w;
    }

    const int bm = (tid >> 5) * 8;     // batch group base (0..56)
    const int n6 = (tid & 31) * 6;     // col offset within tile (0..186)

    for (int t = 0; t < Tt; t++) {
        // ---- stage h chunk [64b][k0..k0+128] into Hs[k][b] ----
        __syncthreads();               // protect Hs/Ws from previous phase
        {
            const float4* h4 = reinterpret_cast<const float4*>(hbase);
#pragma unroll
            for (int i = 0; i < 8; i++) {
                int f = tid + i * 256;     // 0..2047
                int kc4 = f >> 6;          // 0..31
                int b = f & 63;            // lanes vary b -> conflict-free STS
                float4 v = h4[b * (Hh / 4) + (k0 >> 2) + kc4];
                Hs[(kc4 * 4 + 0) * Bb + b] = v.x;
                Hs[(kc4 * 4 + 1) * Bb + b] = v.y;
                Hs[(kc4 * 4 + 2) * Bb + b] = v.z;
                Hs[(kc4 * 4 + 3) * Bb + b] = v.w;
            }
        }
        __syncthreads();

        // ---- microtile GEMM: 8b x 6n per thread, f32x2 packed over b-pairs ----
        unsigned long long acc[4][6];
#pragma unroll
        for (int i = 0; i < 4; i++)
#pragma unroll
            for (int j = 0; j < 6; j++) acc[i][j] = 0ull;

#pragma unroll 4
        for (int k = 0; k < RKC; k++) {
            const float* hrow = Hs + k * Bb + bm;
            ulonglong2 p0 = *reinterpret_cast<const ulonglong2*>(hrow);      // (b0,b1),(b2,b3)
            ulonglong2 p1 = *reinterpret_cast<const ulonglong2*>(hrow + 4);  // (b4,b5),(b6,b7)
            const float* wrow = Ws + k * RTN + n6;
            float2 w01 = *reinterpret_cast<const float2*>(wrow);
            float2 w23 = *reinterpret_cast<const float2*>(wrow + 2);
            float2 w45 = *reinterpret_cast<const float2*>(wrow + 4);
            unsigned long long wd[6];
            wd[0] = pk2(w01.x); wd[1] = pk2(w01.y);
            wd[2] = pk2(w23.x); wd[3] = pk2(w23.y);
            wd[4] = pk2(w45.x); wd[5] = pk2(w45.y);
#pragma unroll
            for (int j = 0; j < 6; j++) {
                fma2(acc[0][j], p0.x, wd[j]);
                fma2(acc[1][j], p0.y, wd[j]);
                fma2(acc[2][j], p1.x, wd[j]);
                fma2(acc[3][j], p1.y, wd[j]);
            }
        }

        // ---- write partials: g_part[kt][b][col] ----
#pragma unroll
        for (int bp = 0; bp < 4; bp++) {
            int b0 = bm + 2 * bp;
            size_t base0 = ((size_t)kt * Bb + b0) * G3 + n0g + n6;
            size_t base1 = base0 + G3;
#pragma unroll
            for (int j = 0; j < 6; j++) {
                float2 c = upk2(acc[bp][j]);
                g_part[base0 + j] = c.x;
                g_part[base1 + j] = c.y;
            }
        }

        grid_bar();   // partials complete

        // ---- fused reduce + gates + state update: 512 elements per block ----
#pragma unroll
        for (int ei = 0; ei < 2; ei++) {
            int e = bid * 512 + ei * 256 + tid;   // 0..65535
            int b = e >> 10;
            int j = e & 1023;

            float hr = bhh[j], hz = bhh[Hh + j], hn = bhh[2 * Hh + j];
#pragma unroll
            for (int ks = 0; ks < RKT; ks++) {
                size_t base = ((size_t)ks * Bb + b) * G3;
                hr += g_part[base + j];
                hz += g_part[base + Hh + j];
                hn += g_part[base + 2 * Hh + j];
            }

            size_t gxb = ((size_t)t * Bb + b) * G3;
            float xr = g_gx[gxb + j];
            float xz = g_gx[gxb + Hh + j];
            float xn = g_gx[gxb + 2 * Hh + j];

            float rg = 1.f / (1.f + expf(-(xr + hr)));
            float zg = 1.f / (1.f + expf(-(xz + hz)));
            float ng = tanhf(xn + rg * hn);

            float hold = hbase[e];
            float hnew = (1.f - zg) * ng + zg * hold;
            g_h[l * Bb * Hh + e] = hnew;

            if (l == 0) {
                g_states[((size_t)t * Bb + b) * Hh + j] = hnew;
                dout[HIDS_OFF + ((size_t)b * Tt + t) * Hh + j] = hnew;
            }
        }

        grid_bar();   // h complete for next step
    }
}

__global__ void finalize(float* __restrict__ dout) {
    int i = blockIdx.x * blockDim.x + threadIdx.x;   // 0 .. B*H-1
    float h0f = g_h[i];
    float h1f = g_h[Bb * Hh + i];
    dout[OUT_OFF + i] = h1f;
    dout[HID_OFF + i] = h0f;
    dout[HID_OFF + Bb * Hh + i] = h1f;
}

// ---------------------------------------------------------------------------
extern "C" void kernel_launch(void* const* d_in, const int* in_sizes, int n_in,
                              void* d_out, int out_size) {
    const int*   x   = (const int*)d_in[0];
    const float* h0  = (const float*)d_in[1];
    const float* emb = (const float*)d_in[2];
    const float* Wih = (const float*)d_in[3];
    const float* Whh = (const float*)d_in[4];
    const float* bih = (const float*)d_in[5];
    const float* bhh = (const float*)d_in[6];
    float* out = (float*)d_out;

    const int dyn_smem = (RKC * RTN + RKC * Bb) * 4;   // 131072 bytes
    cudaFuncSetAttribute(gru_layer_persist,
                         cudaFuncAttributeMaxDynamicSharedMemorySize, dyn_smem);

    init_h<<<(Ll * Bb * Hh + 255) / 256, 256>>>(h0);
    embed_kernel<<<Tt * Bb, Ee / 4>>>(x, emb);

    dim3 ggrid(G3 / GBN, (Tt * Bb) / GBM);      // (24, 256)

    // Layer 0
    sgemm_gx<<<ggrid, 256>>>(0, Wih, bih);
    gru_layer_persist<<<RGRID, 256, dyn_smem>>>(0, Whh, bhh, out);

    // Layer 1
    sgemm_gx<<<ggrid, 256>>>(1, Wih + (size_t)G3 * Ee, bih + G3);
    gru_layer_persist<<<RGRID, 256, dyn_smem>>>(1, Whh, bhh, out);

    finalize<<<(Bb * Hh) / 256, 256>>>(out);
}

// round 10
// speedup vs baseline: 1.1847x; 1.1847x over previous
#include <cuda_runtime.h>
#include <cuda_bf16.h>
#include <cstdint>

// Problem dims (fixed by the dataset)
#define Vv 32000
#define Ee 1024
#define Hh 1024
#define Ll 2
#define Bb 64
#define Tt 512
#define G3 (3*Hh)

// Output packing: (out [1,B,H]) (hidden [L,B,H]) (hiddens [B,T,H])
#define OUT_OFF  0
#define HID_OFF  (Bb*Hh)
#define HIDS_OFF (Bb*Hh + Ll*Bb*Hh)

// Persistent recurrence partitioning
#define RGRID 128
#define RTN   192
#define RKT   8
#define RKC   128

// warp-MMA GEMM tiling
#define MT_M 128
#define MT_N 128
#define KCH  64              // k per staged chunk (bf16)
#define NCHUNK (Ee/KCH)      // 16
#define NPASS 3              // Ahi*Whi + Ahi*Wlo + Alo*Whi
#define PADU 9               // uint4 per padded smem row (72 bf16 = 144B)

// Scratch (device globals: allocation-free per harness rules)
__device__ float g_xs[(size_t)Tt * Bb * Ee];
__device__ float g_states[(size_t)Tt * Bb * Hh];
__device__ float g_gx[(size_t)Tt * Bb * G3];
__device__ float g_part[(size_t)RKT * Bb * G3];
__device__ float g_h[Ll * Bb * Hh];
__device__ __nv_bfloat16 g_Ahi[(size_t)Tt * Bb * Ee];
__device__ __nv_bfloat16 g_Alo[(size_t)Tt * Bb * Ee];
__device__ __nv_bfloat16 g_Whi[(size_t)G3 * Ee];
__device__ __nv_bfloat16 g_Wlo[(size_t)G3 * Ee];

// Grid barrier state
__device__ unsigned g_bar_arrive = 0;
__device__ unsigned g_bar_release = 0;

// ---------------------------------------------------------------------------
// PTX helpers
// ---------------------------------------------------------------------------
__device__ __forceinline__ uint32_t smem_u32(const void* p) {
    uint32_t a;
    asm("{ .reg .u64 t; cvta.to.shared.u64 t, %1; cvt.u32.u64 %0, t; }" : "=r"(a) : "l"(p));
    return a;
}
#define LDSM_X4(r0, r1, r2, r3, a) \
    asm volatile("ldmatrix.sync.aligned.m8n8.x4.shared.b16 {%0,%1,%2,%3}, [%4];" \
                 : "=r"(r0), "=r"(r1), "=r"(r2), "=r"(r3) : "r"(a))
#define MMA16816(d, a, b0, b1) \
    asm volatile("mma.sync.aligned.m16n8k16.row.col.f32.bf16.bf16.f32 " \
                 "{%0,%1,%2,%3}, {%4,%5,%6,%7}, {%8,%9}, {%0,%1,%2,%3};" \
                 : "+f"((d)[0]), "+f"((d)[1]), "+f"((d)[2]), "+f"((d)[3]) \
                 : "r"((a)[0]), "r"((a)[1]), "r"((a)[2]), "r"((a)[3]), \
                   "r"(b0), "r"(b1))

// f32x2 packed helpers
__device__ __forceinline__ unsigned long long pk2(float x) {
    unsigned long long d;
    asm("mov.b64 %0, {%1, %1};" : "=l"(d) : "r"(__float_as_uint(x)));
    return d;
}
__device__ __forceinline__ void fma2(unsigned long long& c, unsigned long long a,
                                     unsigned long long b) {
    asm("fma.rn.f32x2 %0, %1, %2, %0;" : "+l"(c) : "l"(a), "l"(b));
}
__device__ __forceinline__ float2 upk2(unsigned long long d) {
    unsigned lo, hi;
    asm("mov.b64 {%0, %1}, %2;" : "=r"(lo), "=r"(hi) : "l"(d));
    return make_float2(__uint_as_float(lo), __uint_as_float(hi));
}

__device__ __forceinline__ void grid_bar() {
    __syncthreads();
    if (threadIdx.x == 0) {
        __threadfence();
        unsigned gen = *(volatile unsigned*)&g_bar_release;
        unsigned a = atomicAdd(&g_bar_arrive, 1u);
        if (a == RGRID - 1) {
            g_bar_arrive = 0;
            __threadfence();
            atomicAdd(&g_bar_release, 1u);
        } else {
            while (*(volatile unsigned*)&g_bar_release == gen) { __nanosleep(64); }
        }
        __threadfence();
    }
    __syncthreads();
}

// ---------------------------------------------------------------------------
// Embedding + init
// ---------------------------------------------------------------------------
__global__ void embed_kernel(const int* __restrict__ x, const float* __restrict__ emb) {
    int row = blockIdx.x;
    int t = row / Bb;
    int b = row - t * Bb;
    int tok = x[b * Tt + t];
    const float4* src = reinterpret_cast<const float4*>(emb + (size_t)tok * Ee);
    float4* dst = reinterpret_cast<float4*>(g_xs + (size_t)row * Ee);
    dst[threadIdx.x] = src[threadIdx.x];
}

__global__ void init_h(const float* __restrict__ h0) {
    int i = blockIdx.x * blockDim.x + threadIdx.x;
    if (i < Ll * Bb * Hh) g_h[i] = h0[i];
}

// ---------------------------------------------------------------------------
// fp32 -> (bf16 hi, bf16 lo) split conversions.
// NOTE: source selected INSIDE device code (device globals are not valid
// host-side kernel arguments — that was the round-8 fault).
// ---------------------------------------------------------------------------
__global__ void conv_split_A(int from_states) {
    size_t i = (size_t)blockIdx.x * 256 + threadIdx.x;
    float x = from_states ? g_states[i] : g_xs[i];
    __nv_bfloat16 h = __float2bfloat16(x);
    g_Ahi[i] = h;
    g_Alo[i] = __float2bfloat16(x - __bfloat162float(h));
}
__global__ void conv_split_W(const float* __restrict__ src) {
    size_t i = (size_t)blockIdx.x * 256 + threadIdx.x;
    float x = src[i];
    __nv_bfloat16 h = __float2bfloat16(x);
    g_Whi[i] = h;
    g_Wlo[i] = __float2bfloat16(x - __bfloat162float(h));
}

// ---------------------------------------------------------------------------
// bf16-split TN GEMM via mma.sync (HMMA): g_gx[m,n] = sum_k A[m,k]*W[n,k] + bias[n]
// CTA 128x128, 8 warps (2M x 4N), warp tile 64x32, k-chunk 64, 3 passes.
// ---------------------------------------------------------------------------
__global__ __launch_bounds__(256, 2) void gemm_gx_mma(const float* __restrict__ bias) {
    __shared__ __align__(16) __nv_bfloat16 sA[MT_M * PADU * 8];   // 128 rows x 72 bf16
    __shared__ __align__(16) __nv_bfloat16 sB[MT_N * PADU * 8];

    const int tid = threadIdx.x;
    const int wid = tid >> 5, lane = tid & 31;
    const int m0 = blockIdx.y * MT_M;
    const int n0 = blockIdx.x * MT_N;
    const int wm = (wid >> 2) * 64;       // warp m offset: 0 / 64
    const int wn = (wid & 3) * 32;        // warp n offset: 0..96

    const uint32_t sa = smem_u32(sA);
    const uint32_t sb = smem_u32(sB);

    float acc[4][4][4];
#pragma unroll
    for (int i = 0; i < 4; i++)
#pragma unroll
        for (int j = 0; j < 4; j++)
#pragma unroll
            for (int r = 0; r < 4; r++) acc[i][j][r] = 0.f;

    // staging coords: thread handles rows (tid>>3)+32*i, uint4 col (tid&7)
    const int strow = tid >> 3;
    const int stcol = tid & 7;

    // ldmatrix per-lane base offsets
    const int lrow = lane & 15;
    const int lcol = lane >> 4;           // 0 or 1

    for (int pass = 0; pass < NPASS; pass++) {
        const __nv_bfloat16* Asrc = (pass == 2) ? g_Alo : g_Ahi;
        const __nv_bfloat16* Bsrc = (pass == 1) ? g_Wlo : g_Whi;

        for (int c = 0; c < NCHUNK; c++) {
            __syncthreads();
#pragma unroll
            for (int i = 0; i < 4; i++) {
                int r = strow + 32 * i;
                const uint4* ga = reinterpret_cast<const uint4*>(
                    Asrc + (size_t)(m0 + r) * Ee + c * KCH);
                const uint4* gb = reinterpret_cast<const uint4*>(
                    Bsrc + (size_t)(n0 + r) * Ee + c * KCH);
                reinterpret_cast<uint4*>(sA)[r * PADU + stcol] = ga[stcol];
                reinterpret_cast<uint4*>(sB)[r * PADU + stcol] = gb[stcol];
            }
            __syncthreads();

#pragma unroll
            for (int k16 = 0; k16 < KCH / 16; k16++) {
                uint32_t af[4][4];
#pragma unroll
                for (int mt = 0; mt < 4; mt++) {
                    uint32_t addr = sa + ((wm + mt * 16 + lrow) * PADU + k16 * 2 + lcol) * 16;
                    LDSM_X4(af[mt][0], af[mt][1], af[mt][2], af[mt][3], addr);
                }
                uint32_t bf[2][4];
#pragma unroll
                for (int bt = 0; bt < 2; bt++) {
                    uint32_t addr = sb + ((wn + bt * 16 + lrow) * PADU + k16 * 2 + lcol) * 16;
                    LDSM_X4(bf[bt][0], bf[bt][1], bf[bt][2], bf[bt][3], addr);
                }
#pragma unroll
                for (int mt = 0; mt < 4; mt++)
#pragma unroll
                    for (int nt = 0; nt < 4; nt++) {
                        int bt = nt >> 1, lh = nt & 1;
                        MMA16816(acc[mt][nt], af[mt], bf[bt][lh], bf[bt][lh + 2]);
                    }
            }
        }
    }

    // Epilogue: fragment layout -> gmem with bias
    const int er = lane >> 2;            // 0..7
    const int ec = (lane & 3) * 2;       // 0,2,4,6
#pragma unroll
    for (int mt = 0; mt < 4; mt++) {
#pragma unroll
        for (int half = 0; half < 2; half++) {
            int grow = m0 + wm + mt * 16 + er + half * 8;
            size_t base = (size_t)grow * G3;
#pragma unroll
            for (int nt = 0; nt < 4; nt++) {
                int gcol = n0 + wn + nt * 8 + ec;
                float2 v;
                v.x = acc[mt][nt][half * 2 + 0] + bias[gcol];
                v.y = acc[mt][nt][half * 2 + 1] + bias[gcol + 1];
                *reinterpret_cast<float2*>(&g_gx[base + gcol]) = v;
            }
        }
    }
}

// ---------------------------------------------------------------------------
// Persistent recurrence kernel (unchanged — passing)
// ---------------------------------------------------------------------------
extern __shared__ float s_dyn[];

__global__ __launch_bounds__(256, 1) void gru_layer_persist(
    int l, const float* __restrict__ Whh_all, const float* __restrict__ bhh_all,
    float* __restrict__ dout) {

    float* Ws = s_dyn;
    float* Hs = s_dyn + RKC * RTN;

    const int tid = threadIdx.x;
    const int bid = blockIdx.x;
    const int nt = bid & 15;
    const int kt = bid >> 4;
    const int n0g = nt * RTN;
    const int k0 = kt * RKC;

    const float* W = Whh_all + (size_t)l * G3 * Hh;
    const float* bhh = bhh_all + l * G3;
    const float* hbase = g_h + l * Bb * Hh;

    for (int f = tid; f < RTN * (RKC / 4); f += 256) {
        int kc4 = f / RTN;
        int r = f - kc4 * RTN;
        float4 v = *reinterpret_cast<const float4*>(&W[(size_t)(n0g + r) * Hh + k0 + kc4 * 4]);
        Ws[(kc4 * 4 + 0) * RTN + r] = v.x;
        Ws[(kc4 * 4 + 1) * RTN + r] = v.y;
        Ws[(kc4 * 4 + 2) * RTN + r] = v.z;
        Ws[(kc4 * 4 + 3) * RTN + r] = v.w;
    }

    const int bm = (tid >> 5) * 8;
    const int n6 = (tid & 31) * 6;

    for (int t = 0; t < Tt; t++) {
        __syncthreads();
        {
            const float4* h4 = reinterpret_cast<const float4*>(hbase);
#pragma unroll
            for (int i = 0; i < 8; i++) {
                int f = tid + i * 256;
                int kc4 = f >> 6;
                int b = f & 63;
                float4 v = h4[b * (Hh / 4) + (k0 >> 2) + kc4];
                Hs[(kc4 * 4 + 0) * Bb + b] = v.x;
                Hs[(kc4 * 4 + 1) * Bb + b] = v.y;
                Hs[(kc4 * 4 + 2) * Bb + b] = v.z;
                Hs[(kc4 * 4 + 3) * Bb + b] = v.w;
            }
        }
        __syncthreads();

        unsigned long long acc[4][6];
#pragma unroll
        for (int i = 0; i < 4; i++)
#pragma unroll
            for (int j = 0; j < 6; j++) acc[i][j] = 0ull;

#pragma unroll 4
        for (int k = 0; k < RKC; k++) {
            const float* hrow = Hs + k * Bb + bm;
            ulonglong2 p0 = *reinterpret_cast<const ulonglong2*>(hrow);
            ulonglong2 p1 = *reinterpret_cast<const ulonglong2*>(hrow + 4);
            const float* wrow = Ws + k * RTN + n6;
            float2 w01 = *reinterpret_cast<const float2*>(wrow);
            float2 w23 = *reinterpret_cast<const float2*>(wrow + 2);
            float2 w45 = *reinterpret_cast<const float2*>(wrow + 4);
            unsigned long long wd[6];
            wd[0] = pk2(w01.x); wd[1] = pk2(w01.y);
            wd[2] = pk2(w23.x); wd[3] = pk2(w23.y);
            wd[4] = pk2(w45.x); wd[5] = pk2(w45.y);
#pragma unroll
            for (int j = 0; j < 6; j++) {
                fma2(acc[0][j], p0.x, wd[j]);
                fma2(acc[1][j], p0.y, wd[j]);
                fma2(acc[2][j], p1.x, wd[j]);
                fma2(acc[3][j], p1.y, wd[j]);
            }
        }

#pragma unroll
        for (int bp = 0; bp < 4; bp++) {
            int b0 = bm + 2 * bp;
            size_t base0 = ((size_t)kt * Bb + b0) * G3 + n0g + n6;
            size_t base1 = base0 + G3;
#pragma unroll
            for (int j = 0; j < 6; j++) {
                float2 c = upk2(acc[bp][j]);
                g_part[base0 + j] = c.x;
                g_part[base1 + j] = c.y;
            }
        }

        grid_bar();

#pragma unroll
        for (int ei = 0; ei < 2; ei++) {
            int e = bid * 512 + ei * 256 + tid;
            int b = e >> 10;
            int j = e & 1023;

            float hr = bhh[j], hz = bhh[Hh + j], hn = bhh[2 * Hh + j];
#pragma unroll
            for (int ks = 0; ks < RKT; ks++) {
                size_t base = ((size_t)ks * Bb + b) * G3;
                hr += g_part[base + j];
                hz += g_part[base + Hh + j];
                hn += g_part[base + 2 * Hh + j];
            }

            size_t gxb = ((size_t)t * Bb + b) * G3;
            float xr = g_gx[gxb + j];
            float xz = g_gx[gxb + Hh + j];
            float xn = g_gx[gxb + 2 * Hh + j];

            float rg = 1.f / (1.f + expf(-(xr + hr)));
            float zg = 1.f / (1.f + expf(-(xz + hz)));
            float ng = tanhf(xn + rg * hn);

            float hold = hbase[e];
            float hnew = (1.f - zg) * ng + zg * hold;
            g_h[l * Bb * Hh + e] = hnew;

            if (l == 0) {
                g_states[((size_t)t * Bb + b) * Hh + j] = hnew;
                dout[HIDS_OFF + ((size_t)b * Tt + t) * Hh + j] = hnew;
            }
        }

        grid_bar();
    }
}

__global__ void finalize(float* __restrict__ dout) {
    int i = blockIdx.x * blockDim.x + threadIdx.x;
    float h0f = g_h[i];
    float h1f = g_h[Bb * Hh + i];
    dout[OUT_OFF + i] = h1f;
    dout[HID_OFF + i] = h0f;
    dout[HID_OFF + Bb * Hh + i] = h1f;
}

// ---------------------------------------------------------------------------
extern "C" void kernel_launch(void* const* d_in, const int* in_sizes, int n_in,
                              void* d_out, int out_size) {
    const int*   x   = (const int*)d_in[0];
    const float* h0  = (const float*)d_in[1];
    const float* emb = (const float*)d_in[2];
    const float* Wih = (const float*)d_in[3];
    const float* Whh = (const float*)d_in[4];
    const float* bih = (const float*)d_in[5];
    const float* bhh = (const float*)d_in[6];
    float* out = (float*)d_out;

    const int dyn_smem = (RKC * RTN + RKC * Bb) * 4;
    cudaFuncSetAttribute(gru_layer_persist,
                         cudaFuncAttributeMaxDynamicSharedMemorySize, dyn_smem);

    init_h<<<(Ll * Bb * Hh + 255) / 256, 256>>>(h0);
    embed_kernel<<<Tt * Bb, Ee / 4>>>(x, emb);

    dim3 tgrid(G3 / MT_N, (Tt * Bb) / MT_M);    // (24, 256)
    const int nA = (Tt * Bb * Ee) / 256;
    const int nW = (G3 * Ee) / 256;

    // Layer 0
    conv_split_W<<<nW, 256>>>(Wih);
    conv_split_A<<<nA, 256>>>(0);
    gemm_gx_mma<<<tgrid, 256>>>(bih);
    gru_layer_persist<<<RGRID, 256, dyn_smem>>>(0, Whh, bhh, out);

    // Layer 1
    conv_split_W<<<nW, 256>>>(Wih + (size_t)G3 * Ee);
    conv_split_A<<<nA, 256>>>(1);
    gemm_gx_mma<<<tgrid, 256>>>(bih + G3);
    gru_layer_persist<<<RGRID, 256, dyn_smem>>>(1, Whh, bhh, out);

    finalize<<<(Bb * Hh) / 256, 256>>>(out);
}

// round 11
// speedup vs baseline: 1.8404x; 1.5535x over previous
#include <cuda_runtime.h>
#include <cuda_bf16.h>
#include <cstdint>

// Problem dims (fixed by the dataset)
#define Vv 32000
#define Ee 1024
#define Hh 1024
#define Ll 2
#define Bb 64
#define Tt 512
#define G3 (3*Hh)

// Output packing: (out [1,B,H]) (hidden [L,B,H]) (hiddens [B,T,H])
#define OUT_OFF  0
#define HID_OFF  (Bb*Hh)
#define HIDS_OFF (Bb*Hh + Ll*Bb*Hh)

// Persistent recurrence partitioning
#define RGRID 128
#define RTN   192            // cols per n-tile
#define RKT   8              // k-splits
#define RKC   128            // k per split

// warp-MMA GEMM tiling (input-side)
#define MT_M 128
#define MT_N 128
#define KCH  64
#define NCHUNK (Ee/KCH)
#define NPASS 3
#define PADU 9               // uint4 per padded smem row (input gemm)

// recurrence smem row stride: 128 bf16 = 16 uint4, padded to 17 (272B, ≡1 mod 8)
#define PRU 17

// Scratch (device globals: allocation-free per harness rules)
__device__ float g_xs[(size_t)Tt * Bb * Ee];
__device__ float g_states[(size_t)Tt * Bb * Hh];
__device__ float g_gx[(size_t)Tt * Bb * G3];
__device__ float g_part[(size_t)RKT * Bb * G3];
__device__ float g_h[Ll * Bb * Hh];
__device__ __nv_bfloat16 g_Ahi[(size_t)Tt * Bb * Ee];
__device__ __nv_bfloat16 g_Alo[(size_t)Tt * Bb * Ee];
__device__ __nv_bfloat16 g_Whi[(size_t)G3 * Ee];
__device__ __nv_bfloat16 g_Wlo[(size_t)G3 * Ee];

// Grid barrier state
__device__ unsigned g_bar_arrive = 0;
__device__ unsigned g_bar_release = 0;

// ---------------------------------------------------------------------------
// PTX helpers
// ---------------------------------------------------------------------------
__device__ __forceinline__ uint32_t smem_u32(const void* p) {
    uint32_t a;
    asm("{ .reg .u64 t; cvta.to.shared.u64 t, %1; cvt.u32.u64 %0, t; }" : "=r"(a) : "l"(p));
    return a;
}
#define LDSM_X4(r0, r1, r2, r3, a) \
    asm volatile("ldmatrix.sync.aligned.m8n8.x4.shared.b16 {%0,%1,%2,%3}, [%4];" \
                 : "=r"(r0), "=r"(r1), "=r"(r2), "=r"(r3) : "r"(a))
#define MMA16816(d, a, b0, b1) \
    asm volatile("mma.sync.aligned.m16n8k16.row.col.f32.bf16.bf16.f32 " \
                 "{%0,%1,%2,%3}, {%4,%5,%6,%7}, {%8,%9}, {%0,%1,%2,%3};" \
                 : "+f"((d)[0]), "+f"((d)[1]), "+f"((d)[2]), "+f"((d)[3]) \
                 : "r"((a)[0]), "r"((a)[1]), "r"((a)[2]), "r"((a)[3]), \
                   "r"(b0), "r"(b1))

__device__ __forceinline__ uint32_t pk_bf2(float lo, float hi) {
    __nv_bfloat162 t = __floats2bfloat162_rn(lo, hi);
    return *reinterpret_cast<uint32_t*>(&t);
}

__device__ __forceinline__ void grid_bar() {
    __syncthreads();
    if (threadIdx.x == 0) {
        __threadfence();
        unsigned gen = *(volatile unsigned*)&g_bar_release;
        unsigned a = atomicAdd(&g_bar_arrive, 1u);
        if (a == RGRID - 1) {
            g_bar_arrive = 0;
            __threadfence();
            atomicAdd(&g_bar_release, 1u);
        } else {
            while (*(volatile unsigned*)&g_bar_release == gen) { __nanosleep(64); }
        }
        __threadfence();
    }
    __syncthreads();
}

// ---------------------------------------------------------------------------
// Embedding + init
// ---------------------------------------------------------------------------
__global__ void embed_kernel(const int* __restrict__ x, const float* __restrict__ emb) {
    int row = blockIdx.x;
    int t = row / Bb;
    int b = row - t * Bb;
    int tok = x[b * Tt + t];
    const float4* src = reinterpret_cast<const float4*>(emb + (size_t)tok * Ee);
    float4* dst = reinterpret_cast<float4*>(g_xs + (size_t)row * Ee);
    dst[threadIdx.x] = src[threadIdx.x];
}

__global__ void init_h(const float* __restrict__ h0) {
    int i = blockIdx.x * blockDim.x + threadIdx.x;
    if (i < Ll * Bb * Hh) g_h[i] = h0[i];
}

// ---------------------------------------------------------------------------
// fp32 -> (bf16 hi, bf16 lo) split conversions (source chosen in device code)
// ---------------------------------------------------------------------------
__global__ void conv_split_A(int from_states) {
    size_t i = (size_t)blockIdx.x * 256 + threadIdx.x;
    float x = from_states ? g_states[i] : g_xs[i];
    __nv_bfloat16 h = __float2bfloat16(x);
    g_Ahi[i] = h;
    g_Alo[i] = __float2bfloat16(x - __bfloat162float(h));
}
__global__ void conv_split_W(const float* __restrict__ src) {
    size_t i = (size_t)blockIdx.x * 256 + threadIdx.x;
    float x = src[i];
    __nv_bfloat16 h = __float2bfloat16(x);
    g_Whi[i] = h;
    g_Wlo[i] = __float2bfloat16(x - __bfloat162float(h));
}

// ---------------------------------------------------------------------------
// bf16-split TN GEMM via mma.sync (HMMA): g_gx[m,n] = sum_k A[m,k]*W[n,k] + bias[n]
// (unchanged — passing at rel_err 1.14e-5)
// ---------------------------------------------------------------------------
__global__ __launch_bounds__(256, 2) void gemm_gx_mma(const float* __restrict__ bias) {
    __shared__ __align__(16) __nv_bfloat16 sA[MT_M * PADU * 8];
    __shared__ __align__(16) __nv_bfloat16 sB[MT_N * PADU * 8];

    const int tid = threadIdx.x;
    const int wid = tid >> 5, lane = tid & 31;
    const int m0 = blockIdx.y * MT_M;
    const int n0 = blockIdx.x * MT_N;
    const int wm = (wid >> 2) * 64;
    const int wn = (wid & 3) * 32;

    const uint32_t sa = smem_u32(sA);
    const uint32_t sb = smem_u32(sB);

    float acc[4][4][4];
#pragma unroll
    for (int i = 0; i < 4; i++)
#pragma unroll
        for (int j = 0; j < 4; j++)
#pragma unroll
            for (int r = 0; r < 4; r++) acc[i][j][r] = 0.f;

    const int strow = tid >> 3;
    const int stcol = tid & 7;
    const int lrow = lane & 15;
    const int lcol = lane >> 4;

    for (int pass = 0; pass < NPASS; pass++) {
        const __nv_bfloat16* Asrc = (pass == 2) ? g_Alo : g_Ahi;
        const __nv_bfloat16* Bsrc = (pass == 1) ? g_Wlo : g_Whi;

        for (int c = 0; c < NCHUNK; c++) {
            __syncthreads();
#pragma unroll
            for (int i = 0; i < 4; i++) {
                int r = strow + 32 * i;
                const uint4* ga = reinterpret_cast<const uint4*>(
                    Asrc + (size_t)(m0 + r) * Ee + c * KCH);
                const uint4* gb = reinterpret_cast<const uint4*>(
                    Bsrc + (size_t)(n0 + r) * Ee + c * KCH);
                reinterpret_cast<uint4*>(sA)[r * PADU + stcol] = ga[stcol];
                reinterpret_cast<uint4*>(sB)[r * PADU + stcol] = gb[stcol];
            }
            __syncthreads();

#pragma unroll
            for (int k16 = 0; k16 < KCH / 16; k16++) {
                uint32_t af[4][4];
#pragma unroll
                for (int mt = 0; mt < 4; mt++) {
                    uint32_t addr = sa + ((wm + mt * 16 + lrow) * PADU + k16 * 2 + lcol) * 16;
                    LDSM_X4(af[mt][0], af[mt][1], af[mt][2], af[mt][3], addr);
                }
                uint32_t bf[2][4];
#pragma unroll
                for (int bt = 0; bt < 2; bt++) {
                    uint32_t addr = sb + ((wn + bt * 16 + lrow) * PADU + k16 * 2 + lcol) * 16;
                    LDSM_X4(bf[bt][0], bf[bt][1], bf[bt][2], bf[bt][3], addr);
                }
#pragma unroll
                for (int mt = 0; mt < 4; mt++)
#pragma unroll
                    for (int nt = 0; nt < 4; nt++) {
                        int bt = nt >> 1, lh = nt & 1;
                        MMA16816(acc[mt][nt], af[mt], bf[bt][lh], bf[bt][lh + 2]);
                    }
            }
        }
    }

    const int er = lane >> 2;
    const int ec = (lane & 3) * 2;
#pragma unroll
    for (int mt = 0; mt < 4; mt++) {
#pragma unroll
        for (int half = 0; half < 2; half++) {
            int grow = m0 + wm + mt * 16 + er + half * 8;
            size_t base = (size_t)grow * G3;
#pragma unroll
            for (int nt = 0; nt < 4; nt++) {
                int gcol = n0 + wn + nt * 8 + ec;
                float2 v;
                v.x = acc[mt][nt][half * 2 + 0] + bias[gcol];
                v.y = acc[mt][nt][half * 2 + 1] + bias[gcol + 1];
                *reinterpret_cast<float2*>(&g_gx[base + gcol]) = v;
            }
        }
    }
}

// ---------------------------------------------------------------------------
// Persistent recurrence kernel, HMMA edition.
// Block (kt = bid>>4, nt = bid&15): k-slice 128, n-tile 192.
// Smem (dynamic, 139264 B): sHhi/sHlo [64 rows x 136 bf16], sWhi/sWlo [192 x 136].
// Startup: convert W slice to bf16 hi/lo once. Per step: convert h slice,
// 3-pass m16n8k16 (M=batch 64, N=cols 192, K=128), partials, barrier,
// fused reduce+gates (fp32), barrier.
// ---------------------------------------------------------------------------
extern __shared__ __align__(16) unsigned char s_raw[];

__global__ __launch_bounds__(256, 1) void gru_layer_persist(
    int l, const float* __restrict__ Whh_all, const float* __restrict__ bhh_all,
    float* __restrict__ dout) {

    // smem layout in uint4 units
    uint4* s4 = reinterpret_cast<uint4*>(s_raw);
    __nv_bfloat16* sHhi = reinterpret_cast<__nv_bfloat16*>(s4 + 0);       // 64*17
    __nv_bfloat16* sHlo = reinterpret_cast<__nv_bfloat16*>(s4 + 1088);    // 64*17
    __nv_bfloat16* sWhi = reinterpret_cast<__nv_bfloat16*>(s4 + 2176);    // 192*17
    __nv_bfloat16* sWlo = reinterpret_cast<__nv_bfloat16*>(s4 + 5440);    // 192*17

    const int tid = threadIdx.x;
    const int bid = blockIdx.x;
    const int wid = tid >> 5, lane = tid & 31;
    const int nt = bid & 15;
    const int kt = bid >> 4;
    const int n0g = nt * RTN;
    const int k0 = kt * RKC;

    const float* W = Whh_all + (size_t)l * G3 * Hh;
    const float* bhh = bhh_all + l * G3;
    const float* hbase = g_h + l * Bb * Hh;

    // ---- startup: convert W slice [192 rows x 128 k] to bf16 hi/lo in smem ----
    for (int f = tid; f < RTN * 32; f += 256) {      // 6144 float4s
        int r = f >> 5;                               // 0..191
        int c4 = f & 31;                              // float4 index in k-slice
        float4 v = *reinterpret_cast<const float4*>(&W[(size_t)(n0g + r) * Hh + k0 + c4 * 4]);
        __nv_bfloat16 hx = __float2bfloat16(v.x);
        __nv_bfloat16 hy = __float2bfloat16(v.y);
        __nv_bfloat16 hz = __float2bfloat16(v.z);
        __nv_bfloat16 hw = __float2bfloat16(v.w);
        uint32_t* dh = reinterpret_cast<uint32_t*>(sWhi) + r * (PRU * 4) + c4 * 2;
        uint32_t* dl = reinterpret_cast<uint32_t*>(sWlo) + r * (PRU * 4) + c4 * 2;
        dh[0] = pk_bf2(__bfloat162float(hx), __bfloat162float(hy));
        dh[1] = pk_bf2(__bfloat162float(hz), __bfloat162float(hw));
        dl[0] = pk_bf2(v.x - __bfloat162float(hx), v.y - __bfloat162float(hy));
        dl[1] = pk_bf2(v.z - __bfloat162float(hz), v.w - __bfloat162float(hw));
    }

    const uint32_t aHhi = smem_u32(sHhi), aHlo = smem_u32(sHlo);
    const uint32_t aWhi = smem_u32(sWhi), aWlo = smem_u32(sWlo);

    // warp partition: 2 warp-rows over batch (32 each), 4 warp-cols over n (48 each)
    const int wb = (wid >> 2) * 32;
    const int wn = (wid & 3) * 48;
    const int lrow = lane & 15;
    const int lcol = lane >> 4;

    for (int t = 0; t < Tt; t++) {
        // ---- stage h slice [64 b x 128 k] -> bf16 hi/lo smem ----
        __syncthreads();
#pragma unroll
        for (int i = 0; i < 8; i++) {
            int f = tid + i * 256;                   // 0..2047
            int b = f >> 5;                           // 0..63
            int c4 = f & 31;
            float4 v = *reinterpret_cast<const float4*>(&hbase[(size_t)b * Hh + k0 + c4 * 4]);
            __nv_bfloat16 hx = __float2bfloat16(v.x);
            __nv_bfloat16 hy = __float2bfloat16(v.y);
            __nv_bfloat16 hz = __float2bfloat16(v.z);
            __nv_bfloat16 hw = __float2bfloat16(v.w);
            uint32_t* dh = reinterpret_cast<uint32_t*>(sHhi) + b * (PRU * 4) + c4 * 2;
            uint32_t* dl = reinterpret_cast<uint32_t*>(sHlo) + b * (PRU * 4) + c4 * 2;
            dh[0] = pk_bf2(__bfloat162float(hx), __bfloat162float(hy));
            dh[1] = pk_bf2(__bfloat162float(hz), __bfloat162float(hw));
            dl[0] = pk_bf2(v.x - __bfloat162float(hx), v.y - __bfloat162float(hy));
            dl[1] = pk_bf2(v.z - __bfloat162float(hz), v.w - __bfloat162float(hw));
        }
        __syncthreads();

        // ---- 3-pass HMMA: gh[b, n] = sum_k h[b,k] * W[n,k] ----
        float acc[2][6][4];
#pragma unroll
        for (int i = 0; i < 2; i++)
#pragma unroll
            for (int j = 0; j < 6; j++)
#pragma unroll
                for (int r = 0; r < 4; r++) acc[i][j][r] = 0.f;

#pragma unroll
        for (int pass = 0; pass < 3; pass++) {
            const uint32_t aBase = (pass == 2) ? aHlo : aHhi;
            const uint32_t bBase = (pass == 1) ? aWlo : aWhi;
#pragma unroll
            for (int k16 = 0; k16 < RKC / 16; k16++) {
                uint32_t af[2][4];
#pragma unroll
                for (int mt = 0; mt < 2; mt++) {
                    uint32_t addr = aBase + ((wb + mt * 16 + lrow) * PRU + k16 * 2 + lcol) * 16;
                    LDSM_X4(af[mt][0], af[mt][1], af[mt][2], af[mt][3], addr);
                }
                uint32_t bfr[3][4];
#pragma unroll
                for (int bt = 0; bt < 3; bt++) {
                    uint32_t addr = bBase + ((wn + bt * 16 + lrow) * PRU + k16 * 2 + lcol) * 16;
                    LDSM_X4(bfr[bt][0], bfr[bt][1], bfr[bt][2], bfr[bt][3], addr);
                }
#pragma unroll
                for (int mt = 0; mt < 2; mt++)
#pragma unroll
                    for (int ntl = 0; ntl < 6; ntl++) {
                        int bt = ntl >> 1, lh = ntl & 1;
                        MMA16816(acc[mt][ntl], af[mt], bfr[bt][lh], bfr[bt][lh + 2]);
                    }
            }
        }

        // ---- write partials: g_part[kt][b][n0g + wn + ...] ----
        const int er = lane >> 2;
        const int ec = (lane & 3) * 2;
#pragma unroll
        for (int mt = 0; mt < 2; mt++) {
#pragma unroll
            for (int half = 0; half < 2; half++) {
                int b = wb + mt * 16 + er + half * 8;
                size_t rowbase = ((size_t)kt * Bb + b) * G3 + n0g + wn;
#pragma unroll
                for (int ntl = 0; ntl < 6; ntl++) {
                    float2 v;
                    v.x = acc[mt][ntl][half * 2 + 0];
                    v.y = acc[mt][ntl][half * 2 + 1];
                    *reinterpret_cast<float2*>(&g_part[rowbase + ntl * 8 + ec]) = v;
                }
            }
        }

        grid_bar();   // partials complete

        // ---- fused reduce + gates + state update (fp32, unchanged) ----
#pragma unroll
        for (int ei = 0; ei < 2; ei++) {
            int e = bid * 512 + ei * 256 + tid;
            int b = e >> 10;
            int j = e & 1023;

            float hr = bhh[j], hz = bhh[Hh + j], hn = bhh[2 * Hh + j];
#pragma unroll
            for (int ks = 0; ks < RKT; ks++) {
                size_t base = ((size_t)ks * Bb + b) * G3;
                hr += g_part[base + j];
                hz += g_part[base + Hh + j];
                hn += g_part[base + 2 * Hh + j];
            }

            size_t gxb = ((size_t)t * Bb + b) * G3;
            float xr = g_gx[gxb + j];
            float xz = g_gx[gxb + Hh + j];
            float xn = g_gx[gxb + 2 * Hh + j];

            float rg = 1.f / (1.f + expf(-(xr + hr)));
            float zg = 1.f / (1.f + expf(-(xz + hz)));
            float ng = tanhf(xn + rg * hn);

            float hold = hbase[e];
            float hnew = (1.f - zg) * ng + zg * hold;
            g_h[l * Bb * Hh + e] = hnew;

            if (l == 0) {
                g_states[((size_t)t * Bb + b) * Hh + j] = hnew;
                dout[HIDS_OFF + ((size_t)b * Tt + t) * Hh + j] = hnew;
            }
        }

        grid_bar();   // h complete for next step
    }
}

__global__ void finalize(float* __restrict__ dout) {
    int i = blockIdx.x * blockDim.x + threadIdx.x;
    float h0f = g_h[i];
    float h1f = g_h[Bb * Hh + i];
    dout[OUT_OFF + i] = h1f;
    dout[HID_OFF + i] = h0f;
    dout[HID_OFF + Bb * Hh + i] = h1f;
}

// ---------------------------------------------------------------------------
extern "C" void kernel_launch(void* const* d_in, const int* in_sizes, int n_in,
                              void* d_out, int out_size) {
    const int*   x   = (const int*)d_in[0];
    const float* h0  = (const float*)d_in[1];
    const float* emb = (const float*)d_in[2];
    const float* Wih = (const float*)d_in[3];
    const float* Whh = (const float*)d_in[4];
    const float* bih = (const float*)d_in[5];
    const float* bhh = (const float*)d_in[6];
    float* out = (float*)d_out;

    // dynamic smem: (64+64+192+192) rows * 17 uint4 * 16B = 139264 bytes
    const int dyn_smem = (64 + 64 + 192 + 192) * PRU * 16;
    cudaFuncSetAttribute(gru_layer_persist,
                         cudaFuncAttributeMaxDynamicSharedMemorySize, dyn_smem);

    init_h<<<(Ll * Bb * Hh + 255) / 256, 256>>>(h0);
    embed_kernel<<<Tt * Bb, Ee / 4>>>(x, emb);

    dim3 tgrid(G3 / MT_N, (Tt * Bb) / MT_M);    // (24, 256)
    const int nA = (Tt * Bb * Ee) / 256;
    const int nW = (G3 * Ee) / 256;

    // Layer 0
    conv_split_W<<<nW, 256>>>(Wih);
    conv_split_A<<<nA, 256>>>(0);
    gemm_gx_mma<<<tgrid, 256>>>(bih);
    gru_layer_persist<<<RGRID, 256, dyn_smem>>>(0, Whh, bhh, out);

    // Layer 1
    conv_split_W<<<nW, 256>>>(Wih + (size_t)G3 * Ee);
    conv_split_A<<<nA, 256>>>(1);
    gemm_gx_mma<<<tgrid, 256>>>(bih + G3);
    gru_layer_persist<<<RGRID, 256, dyn_smem>>>(1, Whh, bhh, out);

    finalize<<<(Bb * Hh) / 256, 256>>>(out);
}

// round 12
// speedup vs baseline: 1.9318x; 1.0497x over previous
#include <cuda_runtime.h>
#include <cuda_bf16.h>
#include <cstdint>

// Problem dims (fixed by the dataset)
#define Vv 32000
#define Ee 1024
#define Hh 1024
#define Ll 2
#define Bb 64
#define Tt 512
#define G3 (3*Hh)

// Output packing: (out [1,B,H]) (hidden [L,B,H]) (hiddens [B,T,H])
#define OUT_OFF  0
#define HID_OFF  (Bb*Hh)
#define HIDS_OFF (Bb*Hh + Ll*Bb*Hh)

// Persistent recurrence partitioning
#define RGRID 128
#define RTN   192            // cols per n-tile
#define RKT   8              // k-splits
#define RKC   128            // k per split

// warp-MMA GEMM tiling (input-side)
#define MT_M 128
#define MT_N 128
#define KCH  64
#define NPASS 3
#define PADU 9               // uint4 per padded smem row (144B, conflict-free)
#define GSTG 18432           // bytes per A (or B) stage: 128 rows * 144B

// recurrence smem row stride: 16 uint4 padded to 17 (272B)
#define PRU 17

// Scratch (device globals: allocation-free per harness rules)
__device__ float g_gx[(size_t)Tt * Bb * G3];
__device__ float g_part[(size_t)RKT * Bb * G3];
__device__ float g_h[Ll * Bb * Hh];
__device__ __nv_bfloat16 g_Ahi[(size_t)Tt * Bb * Ee];
__device__ __nv_bfloat16 g_Alo[(size_t)Tt * Bb * Ee];
__device__ __nv_bfloat16 g_Whi[(size_t)G3 * Ee];
__device__ __nv_bfloat16 g_Wlo[(size_t)G3 * Ee];

// Grid barrier state (monotonic release counter)
__device__ unsigned g_bar_arrive = 0;
__device__ unsigned g_bar_release = 0;

// ---------------------------------------------------------------------------
// PTX helpers
// ---------------------------------------------------------------------------
__device__ __forceinline__ uint32_t smem_u32(const void* p) {
    uint32_t a;
    asm("{ .reg .u64 t; cvta.to.shared.u64 t, %1; cvt.u32.u64 %0, t; }" : "=r"(a) : "l"(p));
    return a;
}
#define LDSM_X4(r0, r1, r2, r3, a) \
    asm volatile("ldmatrix.sync.aligned.m8n8.x4.shared.b16 {%0,%1,%2,%3}, [%4];" \
                 : "=r"(r0), "=r"(r1), "=r"(r2), "=r"(r3) : "r"(a))
#define MMA16816(d, a, b0, b1) \
    asm volatile("mma.sync.aligned.m16n8k16.row.col.f32.bf16.bf16.f32 " \
                 "{%0,%1,%2,%3}, {%4,%5,%6,%7}, {%8,%9}, {%0,%1,%2,%3};" \
                 : "+f"((d)[0]), "+f"((d)[1]), "+f"((d)[2]), "+f"((d)[3]) \
                 : "r"((a)[0]), "r"((a)[1]), "r"((a)[2]), "r"((a)[3]), \
                   "r"(b0), "r"(b1))
#define CP_ASYNC16(dst, src) \
    asm volatile("cp.async.cg.shared.global [%0], [%1], 16;" :: "r"(dst), "l"(src) : "memory")
#define CP_COMMIT  asm volatile("cp.async.commit_group;" ::: "memory")
#define CP_WAIT1   asm volatile("cp.async.wait_group 1;" ::: "memory")
#define CP_WAIT0   asm volatile("cp.async.wait_group 0;" ::: "memory")

__device__ __forceinline__ uint32_t pk_bf2(float lo, float hi) {
    __nv_bfloat162 t = __floats2bfloat162_rn(lo, hi);
    return *reinterpret_cast<uint32_t*>(&t);
}

// Split grid barrier (monotonic counter; base read at kernel start)
__device__ __forceinline__ void bar_arrive() {
    __syncthreads();
    if (threadIdx.x == 0) {
        __threadfence();
        unsigned a = atomicAdd(&g_bar_arrive, 1u);
        if (a == RGRID - 1) {
            g_bar_arrive = 0;
            __threadfence();
            atomicAdd(&g_bar_release, 1u);
        }
    }
}
__device__ __forceinline__ void bar_wait(unsigned target) {
    if (threadIdx.x == 0) {
        while ((int)(*(volatile unsigned*)&g_bar_release - target) < 0) __nanosleep(32);
        __threadfence();
    }
    __syncthreads();
}

// ---------------------------------------------------------------------------
// Embedding with fused bf16 split: g_Ahi/g_Alo[t*B+b, :] = split(emb[x[b,t], :])
// ---------------------------------------------------------------------------
__global__ void embed_split(const int* __restrict__ x, const float* __restrict__ emb) {
    int row = blockIdx.x;          // t*B + b
    int t = row / Bb;
    int b = row - t * Bb;
    int tok = x[b * Tt + t];
    float4 v = reinterpret_cast<const float4*>(emb + (size_t)tok * Ee)[threadIdx.x];
    float hx = __bfloat162float(__float2bfloat16(v.x));
    float hy = __bfloat162float(__float2bfloat16(v.y));
    float hz = __bfloat162float(__float2bfloat16(v.z));
    float hw = __bfloat162float(__float2bfloat16(v.w));
    uint2 wh = make_uint2(pk_bf2(hx, hy), pk_bf2(hz, hw));
    uint2 wl = make_uint2(pk_bf2(v.x - hx, v.y - hy), pk_bf2(v.z - hz, v.w - hw));
    size_t base = (size_t)row * Ee + threadIdx.x * 4;
    *reinterpret_cast<uint2*>(g_Ahi + base) = wh;
    *reinterpret_cast<uint2*>(g_Alo + base) = wl;
}

__global__ void init_h(const float* __restrict__ h0) {
    int i = blockIdx.x * blockDim.x + threadIdx.x;
    if (i < Ll * Bb * Hh) g_h[i] = h0[i];
}

__global__ void conv_split_W(const float* __restrict__ src) {
    size_t i = (size_t)blockIdx.x * 256 + threadIdx.x;
    float x = src[i];
    __nv_bfloat16 h = __float2bfloat16(x);
    g_Whi[i] = h;
    g_Wlo[i] = __float2bfloat16(x - __bfloat162float(h));
}

// ---------------------------------------------------------------------------
// bf16-split TN GEMM via mma.sync, 2-stage cp.async pipeline.
// g_gx[m,n] = sum_k A[m,k]*W[n,k] + bias[n]; CTA 128x128, 8 warps (2M x 4N).
// Dynamic smem 73728B: A0 @0, A1 @18432, B0 @36864, B1 @55296.
// ---------------------------------------------------------------------------
extern __shared__ __align__(16) unsigned char s_raw[];

__global__ __launch_bounds__(256, 2) void gemm_gx_mma(const float* __restrict__ bias) {
    const int tid = threadIdx.x;
    const int wid = tid >> 5, lane = tid & 31;
    const int m0 = blockIdx.y * MT_M;
    const int n0 = blockIdx.x * MT_N;
    const int wm = (wid >> 2) * 64;
    const int wn = (wid & 3) * 32;

    const uint32_t sbase = smem_u32(s_raw);
    const int strow = tid >> 3;
    const int stcol = tid & 7;
    const int lrow = lane & 15;
    const int lcol = lane >> 4;

    float acc[4][4][4];
#pragma unroll
    for (int i = 0; i < 4; i++)
#pragma unroll
        for (int j = 0; j < 4; j++)
#pragma unroll
            for (int r = 0; r < 4; r++) acc[i][j][r] = 0.f;

    auto issue_chunk = [&](int c, int s) {
        int pass = c >> 4, cc = c & 15;
        const __nv_bfloat16* Asrc = (pass == 2) ? g_Alo : g_Ahi;
        const __nv_bfloat16* Bsrc = (pass == 1) ? g_Wlo : g_Whi;
#pragma unroll
        for (int i = 0; i < 4; i++) {
            int r = strow + 32 * i;
            const __nv_bfloat16* ga = Asrc + (size_t)(m0 + r) * Ee + cc * KCH + stcol * 8;
            const __nv_bfloat16* gb = Bsrc + (size_t)(n0 + r) * Ee + cc * KCH + stcol * 8;
            uint32_t off = (uint32_t)(r * PADU + stcol) * 16 + s * GSTG;
            CP_ASYNC16(sbase + off, ga);
            CP_ASYNC16(sbase + 2 * GSTG + off, gb);
        }
    };

    issue_chunk(0, 0);
    CP_COMMIT;

    for (int c = 0; c < NPASS * 16; c++) {
        if (c < NPASS * 16 - 1) {
            issue_chunk(c + 1, (c + 1) & 1);
            CP_COMMIT;
            CP_WAIT1;
        } else {
            CP_WAIT0;
        }
        __syncthreads();

        const uint32_t sa = sbase + (c & 1) * GSTG;
        const uint32_t sb = sbase + 2 * GSTG + (c & 1) * GSTG;
#pragma unroll
        for (int k16 = 0; k16 < KCH / 16; k16++) {
            uint32_t af[4][4];
#pragma unroll
            for (int mt = 0; mt < 4; mt++) {
                uint32_t addr = sa + ((wm + mt * 16 + lrow) * PADU + k16 * 2 + lcol) * 16;
                LDSM_X4(af[mt][0], af[mt][1], af[mt][2], af[mt][3], addr);
            }
            uint32_t bf[2][4];
#pragma unroll
            for (int bt = 0; bt < 2; bt++) {
                uint32_t addr = sb + ((wn + bt * 16 + lrow) * PADU + k16 * 2 + lcol) * 16;
                LDSM_X4(bf[bt][0], bf[bt][1], bf[bt][2], bf[bt][3], addr);
            }
#pragma unroll
            for (int mt = 0; mt < 4; mt++)
#pragma unroll
                for (int nt = 0; nt < 4; nt++) {
                    int bt = nt >> 1, lh = nt & 1;
                    MMA16816(acc[mt][nt], af[mt], bf[bt][lh], bf[bt][lh + 2]);
                }
        }
        __syncthreads();
    }

    // Epilogue: fragment layout -> gmem with bias
    const int er = lane >> 2;
    const int ec = (lane & 3) * 2;
#pragma unroll
    for (int mt = 0; mt < 4; mt++) {
#pragma unroll
        for (int half = 0; half < 2; half++) {
            int grow = m0 + wm + mt * 16 + er + half * 8;
            size_t base = (size_t)grow * G3;
#pragma unroll
            for (int nt = 0; nt < 4; nt++) {
                int gcol = n0 + wn + nt * 8 + ec;
                float2 v;
                v.x = acc[mt][nt][half * 2 + 0] + bias[gcol];
                v.y = acc[mt][nt][half * 2 + 1] + bias[gcol + 1];
                *reinterpret_cast<float2*>(&g_gx[base + gcol]) = v;
            }
        }
    }
}

// ---------------------------------------------------------------------------
// Persistent recurrence kernel, HMMA + split barrier + prefetch.
// Block (kt = bid>>4, nt = bid&15). Smem 139264B:
// sHhi/sHlo [64 x 17u4], sWhi/sWlo [192 x 17u4].
// ---------------------------------------------------------------------------
__global__ __launch_bounds__(256, 1) void gru_layer_persist(
    int l, const float* __restrict__ Whh_all, const float* __restrict__ bhh_all,
    float* __restrict__ dout) {

    uint4* s4 = reinterpret_cast<uint4*>(s_raw);
    __nv_bfloat16* sHhi = reinterpret_cast<__nv_bfloat16*>(s4 + 0);
    __nv_bfloat16* sHlo = reinterpret_cast<__nv_bfloat16*>(s4 + 1088);
    __nv_bfloat16* sWhi = reinterpret_cast<__nv_bfloat16*>(s4 + 2176);
    __nv_bfloat16* sWlo = reinterpret_cast<__nv_bfloat16*>(s4 + 5440);

    const int tid = threadIdx.x;
    const int bid = blockIdx.x;
    const int wid = tid >> 5, lane = tid & 31;
    const int nt = bid & 15;
    const int kt = bid >> 4;
    const int n0g = nt * RTN;
    const int k0 = kt * RKC;

    const float* W = Whh_all + (size_t)l * G3 * Hh;
    const float* bhh = bhh_all + l * G3;
    const float* hbase = g_h + l * Bb * Hh;

    __shared__ unsigned s_base0;
    if (tid == 0) s_base0 = *(volatile unsigned*)&g_bar_release;

    // ---- startup: convert W slice [192 x 128] to bf16 hi/lo in smem ----
    for (int f = tid; f < RTN * 32; f += 256) {
        int r = f >> 5;
        int c4 = f & 31;
        float4 v = *reinterpret_cast<const float4*>(&W[(size_t)(n0g + r) * Hh + k0 + c4 * 4]);
        float hx = __bfloat162float(__float2bfloat16(v.x));
        float hy = __bfloat162float(__float2bfloat16(v.y));
        float hz = __bfloat162float(__float2bfloat16(v.z));
        float hw = __bfloat162float(__float2bfloat16(v.w));
        uint32_t* dh = reinterpret_cast<uint32_t*>(sWhi) + r * (PRU * 4) + c4 * 2;
        uint32_t* dl = reinterpret_cast<uint32_t*>(sWlo) + r * (PRU * 4) + c4 * 2;
        dh[0] = pk_bf2(hx, hy);
        dh[1] = pk_bf2(hz, hw);
        dl[0] = pk_bf2(v.x - hx, v.y - hy);
        dl[1] = pk_bf2(v.z - hz, v.w - hw);
    }
    __syncthreads();
    const unsigned bar_base = s_base0;
    unsigned gen = 0;

    const uint32_t aHhi = smem_u32(sHhi), aHlo = smem_u32(sHlo);
    const uint32_t aWhi = smem_u32(sWhi), aWlo = smem_u32(sWlo);

    const int wb = (wid >> 2) * 32;
    const int wn = (wid & 3) * 48;
    const int lrow = lane & 15;
    const int lcol = lane >> 4;
    const int er = lane >> 2;
    const int ec = (lane & 3) * 2;

    // gate-phase constants (element ids fixed per thread)
    int e_[2], b_[2], j_[2];
    float br_[2], bz_[2], bn_[2];
#pragma unroll
    for (int ei = 0; ei < 2; ei++) {
        e_[ei] = bid * 512 + ei * 256 + tid;
        b_[ei] = e_[ei] >> 10;
        j_[ei] = e_[ei] & 1023;
        br_[ei] = bhh[j_[ei]];
        bz_[ei] = bhh[Hh + j_[ei]];
        bn_[ei] = bhh[2 * Hh + j_[ei]];
    }

    for (int t = 0; t < Tt; t++) {
        // ---- stage h slice [64 x 128] -> bf16 hi/lo smem ----
        __syncthreads();
#pragma unroll
        for (int i = 0; i < 8; i++) {
            int f = tid + i * 256;
            int b = f >> 5;
            int c4 = f & 31;
            float4 v = *reinterpret_cast<const float4*>(&hbase[(size_t)b * Hh + k0 + c4 * 4]);
            float hx = __bfloat162float(__float2bfloat16(v.x));
            float hy = __bfloat162float(__float2bfloat16(v.y));
            float hz = __bfloat162float(__float2bfloat16(v.z));
            float hw = __bfloat162float(__float2bfloat16(v.w));
            uint32_t* dh = reinterpret_cast<uint32_t*>(sHhi) + b * (PRU * 4) + c4 * 2;
            uint32_t* dl = reinterpret_cast<uint32_t*>(sHlo) + b * (PRU * 4) + c4 * 2;
            dh[0] = pk_bf2(hx, hy);
            dh[1] = pk_bf2(hz, hw);
            dl[0] = pk_bf2(v.x - hx, v.y - hy);
            dl[1] = pk_bf2(v.z - hz, v.w - hw);
        }
        __syncthreads();

        // ---- 3-pass HMMA: gh[b, n] = sum_k h[b,k] * W[n,k] ----
        float acc[2][6][4];
#pragma unroll
        for (int i = 0; i < 2; i++)
#pragma unroll
            for (int j = 0; j < 6; j++)
#pragma unroll
                for (int r = 0; r < 4; r++) acc[i][j][r] = 0.f;

#pragma unroll
        for (int pass = 0; pass < 3; pass++) {
            const uint32_t aBase = (pass == 2) ? aHlo : aHhi;
            const uint32_t bBase = (pass == 1) ? aWlo : aWhi;
#pragma unroll
            for (int k16 = 0; k16 < RKC / 16; k16++) {
                uint32_t af[2][4];
#pragma unroll
                for (int mt = 0; mt < 2; mt++) {
                    uint32_t addr = aBase + ((wb + mt * 16 + lrow) * PRU + k16 * 2 + lcol) * 16;
                    LDSM_X4(af[mt][0], af[mt][1], af[mt][2], af[mt][3], addr);
                }
                uint32_t bfr[3][4];
#pragma unroll
                for (int bt = 0; bt < 3; bt++) {
                    uint32_t addr = bBase + ((wn + bt * 16 + lrow) * PRU + k16 * 2 + lcol) * 16;
                    LDSM_X4(bfr[bt][0], bfr[bt][1], bfr[bt][2], bfr[bt][3], addr);
                }
#pragma unroll
                for (int mt = 0; mt < 2; mt++)
#pragma unroll
                    for (int ntl = 0; ntl < 6; ntl++) {
                        int bt = ntl >> 1, lh = ntl & 1;
                        MMA16816(acc[mt][ntl], af[mt], bfr[bt][lh], bfr[bt][lh + 2]);
                    }
            }
        }

        // ---- write partials ----
#pragma unroll
        for (int mt = 0; mt < 2; mt++) {
#pragma unroll
            for (int half = 0; half < 2; half++) {
                int b = wb + mt * 16 + er + half * 8;
                size_t rowbase = ((size_t)kt * Bb + b) * G3 + n0g + wn;
#pragma unroll
                for (int ntl = 0; ntl < 6; ntl++) {
                    float2 v;
                    v.x = acc[mt][ntl][half * 2 + 0];
                    v.y = acc[mt][ntl][half * 2 + 1];
                    *reinterpret_cast<float2*>(&g_part[rowbase + ntl * 8 + ec]) = v;
                }
            }
        }

        bar_arrive();   // barrier 1 arrive
        ++gen;

        // prefetch gate inputs (block-private elements; race-free)
        float xr_[2], xz_[2], xn_[2], hold_[2];
#pragma unroll
        for (int ei = 0; ei < 2; ei++) {
            size_t gxb = ((size_t)t * Bb + b_[ei]) * G3;
            xr_[ei] = g_gx[gxb + j_[ei]];
            xz_[ei] = g_gx[gxb + Hh + j_[ei]];
            xn_[ei] = g_gx[gxb + 2 * Hh + j_[ei]];
            hold_[ei] = hbase[e_[ei]];
        }

        bar_wait(bar_base + gen);   // barrier 1 wait (partials visible)

        // ---- fused reduce + gates + state update ----
#pragma unroll
        for (int ei = 0; ei < 2; ei++) {
            int b = b_[ei], j = j_[ei];
            float hr = br_[ei], hz = bz_[ei], hn = bn_[ei];
#pragma unroll
            for (int ks = 0; ks < RKT; ks++) {
                size_t base = ((size_t)ks * Bb + b) * G3;
                hr += g_part[base + j];
                hz += g_part[base + Hh + j];
                hn += g_part[base + 2 * Hh + j];
            }

            float rg = 1.f / (1.f + expf(-(xr_[ei] + hr)));
            float zg = 1.f / (1.f + expf(-(xz_[ei] + hz)));
            float ng = tanhf(xn_[ei] + rg * hn);

            float hnew = (1.f - zg) * ng + zg * hold_[ei];
            g_h[l * Bb * Hh + e_[ei]] = hnew;

            if (l == 0) {
                // bf16 split of the state feeds layer-1's input GEMM directly
                size_t arow = ((size_t)t * Bb + b) * Ee + j;
                __nv_bfloat16 hh = __float2bfloat16(hnew);
                g_Ahi[arow] = hh;
                g_Alo[arow] = __float2bfloat16(hnew - __bfloat162float(hh));
                dout[HIDS_OFF + ((size_t)b * Tt + t) * Hh + j] = hnew;
            }
        }

        bar_arrive();   // barrier 2
        ++gen;
        bar_wait(bar_base + gen);
    }
}

__global__ void finalize(float* __restrict__ dout) {
    int i = blockIdx.x * blockDim.x + threadIdx.x;
    float h0f = g_h[i];
    float h1f = g_h[Bb * Hh + i];
    dout[OUT_OFF + i] = h1f;
    dout[HID_OFF + i] = h0f;
    dout[HID_OFF + Bb * Hh + i] = h1f;
}

// ---------------------------------------------------------------------------
extern "C" void kernel_launch(void* const* d_in, const int* in_sizes, int n_in,
                              void* d_out, int out_size) {
    const int*   x   = (const int*)d_in[0];
    const float* h0  = (const float*)d_in[1];
    const float* emb = (const float*)d_in[2];
    const float* Wih = (const float*)d_in[3];
    const float* Whh = (const float*)d_in[4];
    const float* bih = (const float*)d_in[5];
    const float* bhh = (const float*)d_in[6];
    float* out = (float*)d_out;

    const int gemm_smem = 4 * GSTG;                          // 73728
    const int rec_smem = (64 + 64 + 192 + 192) * PRU * 16;   // 139264
    cudaFuncSetAttribute(gemm_gx_mma,
                         cudaFuncAttributeMaxDynamicSharedMemorySize, gemm_smem);
    cudaFuncSetAttribute(gru_layer_persist,
                         cudaFuncAttributeMaxDynamicSharedMemorySize, rec_smem);

    init_h<<<(Ll * Bb * Hh + 255) / 256, 256>>>(h0);
    embed_split<<<Tt * Bb, Ee / 4>>>(x, emb);

    dim3 tgrid(G3 / MT_N, (Tt * Bb) / MT_M);    // (24, 256)
    const int nW = (G3 * Ee) / 256;

    // Layer 0
    conv_split_W<<<nW, 256>>>(Wih);
    gemm_gx_mma<<<tgrid, 256, gemm_smem>>>(bih);
    gru_layer_persist<<<RGRID, 256, rec_smem>>>(0, Whh, bhh, out);

    // Layer 1 (A = bf16 split of layer-0 states, written by the gate phase)
    conv_split_W<<<nW, 256>>>(Wih + (size_t)G3 * Ee);
    gemm_gx_mma<<<tgrid, 256, gemm_smem>>>(bih + G3);
    gru_layer_persist<<<RGRID, 256, rec_smem>>>(1, Whh, bhh, out);

    finalize<<<(Bb * Hh) / 256, 256>>>(out);
}

// round 13
// speedup vs baseline: 2.3375x; 1.2100x over previous
#include <cuda_runtime.h>
#include <cuda_bf16.h>
#include <cuda_fp16.h>
#include <cstdint>

// Problem dims (fixed by the dataset)
#define Vv 32000
#define Ee 1024
#define Hh 1024
#define Ll 2
#define Bb 64
#define Tt 512
#define G3 (3*Hh)

// Output packing: (out [1,B,H]) (hidden [L,B,H]) (hiddens [B,T,H])
#define OUT_OFF  0
#define HID_OFF  (Bb*Hh)
#define HIDS_OFF (Bb*Hh + Ll*Bb*Hh)

// Persistent recurrence partitioning
#define RGRID 128
#define RTN   192            // cols per n-tile
#define RKT   8              // k-splits
#define RKC   128            // k per split

// warp-MMA GEMM tiling (input-side)
#define MT_M 128
#define MT_N 128
#define KCH  64
#define NPASS 2              // fp16 hi*hi + bf16 lo*W
#define PADU 9               // uint4 per padded smem row (144B, conflict-free)
#define GSTG 18432           // bytes per A (or B) stage: 128 rows * 144B

// recurrence smem row stride: 16 uint4 padded to 17 (272B)
#define PRU 17

// Scratch (device globals: allocation-free per harness rules)
// 16-bit payloads stored as raw bits: Ahi/Whi = fp16, Alo/Wbf = bf16
__device__ float g_gx[(size_t)Tt * Bb * G3];
__device__ float g_part[(size_t)RKT * Bb * G3];
__device__ float g_h[Ll * Bb * Hh];
__device__ uint16_t g_Ahi[(size_t)Tt * Bb * Ee];   // fp16(A)
__device__ uint16_t g_Alo[(size_t)Tt * Bb * Ee];   // bf16(A - fp16(A))
__device__ uint16_t g_Whi[(size_t)G3 * Ee];        // fp16(W)
__device__ uint16_t g_Wbf[(size_t)G3 * Ee];        // bf16(W)

// Grid barrier state (monotonic release counter)
__device__ unsigned g_bar_arrive = 0;
__device__ unsigned g_bar_release = 0;

// ---------------------------------------------------------------------------
// PTX helpers
// ---------------------------------------------------------------------------
__device__ __forceinline__ uint32_t smem_u32(const void* p) {
    uint32_t a;
    asm("{ .reg .u64 t; cvta.to.shared.u64 t, %1; cvt.u32.u64 %0, t; }" : "=r"(a) : "l"(p));
    return a;
}
#define LDSM_X4(r0, r1, r2, r3, a) \
    asm volatile("ldmatrix.sync.aligned.m8n8.x4.shared.b16 {%0,%1,%2,%3}, [%4];" \
                 : "=r"(r0), "=r"(r1), "=r"(r2), "=r"(r3) : "r"(a))
#define MMA_BF16(d, a, b0, b1) \
    asm volatile("mma.sync.aligned.m16n8k16.row.col.f32.bf16.bf16.f32 " \
                 "{%0,%1,%2,%3}, {%4,%5,%6,%7}, {%8,%9}, {%0,%1,%2,%3};" \
                 : "+f"((d)[0]), "+f"((d)[1]), "+f"((d)[2]), "+f"((d)[3]) \
                 : "r"((a)[0]), "r"((a)[1]), "r"((a)[2]), "r"((a)[3]), \
                   "r"(b0), "r"(b1))
#define MMA_F16(d, a, b0, b1) \
    asm volatile("mma.sync.aligned.m16n8k16.row.col.f32.f16.f16.f32 " \
                 "{%0,%1,%2,%3}, {%4,%5,%6,%7}, {%8,%9}, {%0,%1,%2,%3};" \
                 : "+f"((d)[0]), "+f"((d)[1]), "+f"((d)[2]), "+f"((d)[3]) \
                 : "r"((a)[0]), "r"((a)[1]), "r"((a)[2]), "r"((a)[3]), \
                   "r"(b0), "r"(b1))
#define CP_ASYNC16(dst, src) \
    asm volatile("cp.async.cg.shared.global [%0], [%1], 16;" :: "r"(dst), "l"(src) : "memory")
#define CP_COMMIT  asm volatile("cp.async.commit_group;" ::: "memory")
#define CP_WAIT1   asm volatile("cp.async.wait_group 1;" ::: "memory")
#define CP_WAIT0   asm volatile("cp.async.wait_group 0;" ::: "memory")

__device__ __forceinline__ uint32_t pk_bf2(float lo, float hi) {
    __nv_bfloat162 t = __floats2bfloat162_rn(lo, hi);
    return *reinterpret_cast<uint32_t*>(&t);
}
__device__ __forceinline__ uint32_t pk_h2(float lo, float hi) {
    __half2 t = __floats2half2_rn(lo, hi);
    return *reinterpret_cast<uint32_t*>(&t);
}

// Split grid barrier (monotonic counter; base read at kernel start)
__device__ __forceinline__ void bar_arrive() {
    __syncthreads();
    if (threadIdx.x == 0) {
        __threadfence();
        unsigned a = atomicAdd(&g_bar_arrive, 1u);
        if (a == RGRID - 1) {
            g_bar_arrive = 0;
            __threadfence();
            atomicAdd(&g_bar_release, 1u);
        }
    }
}
__device__ __forceinline__ void bar_wait(unsigned target) {
    if (threadIdx.x == 0) {
        while ((int)(*(volatile unsigned*)&g_bar_release - target) < 0) __nanosleep(32);
        __threadfence();
    }
    __syncthreads();
}

// ---------------------------------------------------------------------------
// Embedding with fused fp16/bf16 split
// ---------------------------------------------------------------------------
__global__ void embed_split(const int* __restrict__ x, const float* __restrict__ emb) {
    int row = blockIdx.x;          // t*B + b
    int t = row / Bb;
    int b = row - t * Bb;
    int tok = x[b * Tt + t];
    float4 v = reinterpret_cast<const float4*>(emb + (size_t)tok * Ee)[threadIdx.x];
    float hx = __half2float(__float2half_rn(v.x));
    float hy = __half2float(__float2half_rn(v.y));
    float hz = __half2float(__float2half_rn(v.z));
    float hw = __half2float(__float2half_rn(v.w));
    uint2 wh = make_uint2(pk_h2(hx, hy), pk_h2(hz, hw));
    uint2 wl = make_uint2(pk_bf2(v.x - hx, v.y - hy), pk_bf2(v.z - hz, v.w - hw));
    size_t base = (size_t)row * Ee + threadIdx.x * 4;
    *reinterpret_cast<uint2*>(g_Ahi + base) = wh;
    *reinterpret_cast<uint2*>(g_Alo + base) = wl;
}

__global__ void init_h(const float* __restrict__ h0) {
    int i = blockIdx.x * blockDim.x + threadIdx.x;
    if (i < Ll * Bb * Hh) g_h[i] = h0[i];
}

__global__ void conv_split_W(const float* __restrict__ src) {
    size_t i = (size_t)blockIdx.x * 256 + threadIdx.x;
    float x = src[i];
    __half h = __float2half_rn(x);
    __nv_bfloat16 b = __float2bfloat16(x);
    g_Whi[i] = *reinterpret_cast<uint16_t*>(&h);
    g_Wbf[i] = *reinterpret_cast<uint16_t*>(&b);
}

// ---------------------------------------------------------------------------
// 2-pass split TN GEMM via mma.sync: g_gx[m,n] = sum_k A[m,k]*W[n,k] + bias[n]
// pass0: fp16(A)x fp16(W); pass1: bf16lo(A) x bf16(W). cp.async 2-stage.
// ---------------------------------------------------------------------------
extern __shared__ __align__(16) unsigned char s_raw[];

__global__ __launch_bounds__(256, 2) void gemm_gx_mma(const float* __restrict__ bias) {
    const int tid = threadIdx.x;
    const int wid = tid >> 5, lane = tid & 31;
    const int m0 = blockIdx.y * MT_M;
    const int n0 = blockIdx.x * MT_N;
    const int wm = (wid >> 2) * 64;
    const int wn = (wid & 3) * 32;

    const uint32_t sbase = smem_u32(s_raw);
    const int strow = tid >> 3;
    const int stcol = tid & 7;
    const int lrow = lane & 15;
    const int lcol = lane >> 4;

    float acc[4][4][4];
#pragma unroll
    for (int i = 0; i < 4; i++)
#pragma unroll
        for (int j = 0; j < 4; j++)
#pragma unroll
            for (int r = 0; r < 4; r++) acc[i][j][r] = 0.f;

    auto issue_chunk = [&](int c, int s) {
        int pass = c >> 4, cc = c & 15;
        const uint16_t* Asrc = pass ? g_Alo : g_Ahi;
        const uint16_t* Bsrc = pass ? g_Wbf : g_Whi;
#pragma unroll
        for (int i = 0; i < 4; i++) {
            int r = strow + 32 * i;
            const uint16_t* ga = Asrc + (size_t)(m0 + r) * Ee + cc * KCH + stcol * 8;
            const uint16_t* gb = Bsrc + (size_t)(n0 + r) * Ee + cc * KCH + stcol * 8;
            uint32_t off = (uint32_t)(r * PADU + stcol) * 16 + s * GSTG;
            CP_ASYNC16(sbase + off, ga);
            CP_ASYNC16(sbase + 2 * GSTG + off, gb);
        }
    };

    issue_chunk(0, 0);
    CP_COMMIT;

    for (int c = 0; c < NPASS * 16; c++) {
        if (c < NPASS * 16 - 1) {
            issue_chunk(c + 1, (c + 1) & 1);
            CP_COMMIT;
            CP_WAIT1;
        } else {
            CP_WAIT0;
        }
        __syncthreads();

        const uint32_t sa = sbase + (c & 1) * GSTG;
        const uint32_t sb = sbase + 2 * GSTG + (c & 1) * GSTG;
#pragma unroll
        for (int k16 = 0; k16 < KCH / 16; k16++) {
            uint32_t af[4][4];
#pragma unroll
            for (int mt = 0; mt < 4; mt++) {
                uint32_t addr = sa + ((wm + mt * 16 + lrow) * PADU + k16 * 2 + lcol) * 16;
                LDSM_X4(af[mt][0], af[mt][1], af[mt][2], af[mt][3], addr);
            }
            uint32_t bf[2][4];
#pragma unroll
            for (int bt = 0; bt < 2; bt++) {
                uint32_t addr = sb + ((wn + bt * 16 + lrow) * PADU + k16 * 2 + lcol) * 16;
                LDSM_X4(bf[bt][0], bf[bt][1], bf[bt][2], bf[bt][3], addr);
            }
            if (c < 16) {
#pragma unroll
                for (int mt = 0; mt < 4; mt++)
#pragma unroll
                    for (int nt = 0; nt < 4; nt++) {
                        int bt = nt >> 1, lh = nt & 1;
                        MMA_F16(acc[mt][nt], af[mt], bf[bt][lh], bf[bt][lh + 2]);
                    }
            } else {
#pragma unroll
                for (int mt = 0; mt < 4; mt++)
#pragma unroll
                    for (int nt = 0; nt < 4; nt++) {
                        int bt = nt >> 1, lh = nt & 1;
                        MMA_BF16(acc[mt][nt], af[mt], bf[bt][lh], bf[bt][lh + 2]);
                    }
            }
        }
        __syncthreads();
    }

    // Epilogue: fragment layout -> gmem with bias
    const int er = lane >> 2;
    const int ec = (lane & 3) * 2;
#pragma unroll
    for (int mt = 0; mt < 4; mt++) {
#pragma unroll
        for (int half = 0; half < 2; half++) {
            int grow = m0 + wm + mt * 16 + er + half * 8;
            size_t base = (size_t)grow * G3;
#pragma unroll
            for (int nt = 0; nt < 4; nt++) {
                int gcol = n0 + wn + nt * 8 + ec;
                float2 v;
                v.x = acc[mt][nt][half * 2 + 0] + bias[gcol];
                v.y = acc[mt][nt][half * 2 + 1] + bias[gcol + 1];
                *reinterpret_cast<float2*>(&g_gx[base + gcol]) = v;
            }
        }
    }
}

// ---------------------------------------------------------------------------
// Persistent recurrence kernel, 2-pass HMMA + split barrier + prefetch.
// Smem: sH16/sHlb [64 x 17u4], sW16/sWb [192 x 17u4]  (139264 B)
// ---------------------------------------------------------------------------
__global__ __launch_bounds__(256, 1) void gru_layer_persist(
    int l, const float* __restrict__ Whh_all, const float* __restrict__ bhh_all,
    float* __restrict__ dout) {

    uint4* s4 = reinterpret_cast<uint4*>(s_raw);
    uint16_t* sH16 = reinterpret_cast<uint16_t*>(s4 + 0);
    uint16_t* sHlb = reinterpret_cast<uint16_t*>(s4 + 1088);
    uint16_t* sW16 = reinterpret_cast<uint16_t*>(s4 + 2176);
    uint16_t* sWb  = reinterpret_cast<uint16_t*>(s4 + 5440);

    const int tid = threadIdx.x;
    const int bid = blockIdx.x;
    const int wid = tid >> 5, lane = tid & 31;
    const int nt = bid & 15;
    const int kt = bid >> 4;
    const int n0g = nt * RTN;
    const int k0 = kt * RKC;

    const float* W = Whh_all + (size_t)l * G3 * Hh;
    const float* bhh = bhh_all + l * G3;
    const float* hbase = g_h + l * Bb * Hh;

    __shared__ unsigned s_base0;
    if (tid == 0) s_base0 = *(volatile unsigned*)&g_bar_release;

    // ---- startup: W slice [192 x 128] -> fp16 + bf16 in smem ----
    for (int f = tid; f < RTN * 32; f += 256) {
        int r = f >> 5;
        int c4 = f & 31;
        float4 v = *reinterpret_cast<const float4*>(&W[(size_t)(n0g + r) * Hh + k0 + c4 * 4]);
        uint32_t* dh = reinterpret_cast<uint32_t*>(sW16) + r * (PRU * 4) + c4 * 2;
        uint32_t* db = reinterpret_cast<uint32_t*>(sWb)  + r * (PRU * 4) + c4 * 2;
        dh[0] = pk_h2(v.x, v.y);
        dh[1] = pk_h2(v.z, v.w);
        db[0] = pk_bf2(v.x, v.y);
        db[1] = pk_bf2(v.z, v.w);
    }
    __syncthreads();
    const unsigned bar_base = s_base0;
    unsigned gen = 0;

    const uint32_t aH16 = smem_u32(sH16), aHlb = smem_u32(sHlb);
    const uint32_t aW16 = smem_u32(sW16), aWb = smem_u32(sWb);

    const int wb = (wid >> 2) * 32;
    const int wn = (wid & 3) * 48;
    const int lrow = lane & 15;
    const int lcol = lane >> 4;
    const int er = lane >> 2;
    const int ec = (lane & 3) * 2;

    // gate-phase constants
    int e_[2], b_[2], j_[2];
    float br_[2], bz_[2], bn_[2];
#pragma unroll
    for (int ei = 0; ei < 2; ei++) {
        e_[ei] = bid * 512 + ei * 256 + tid;
        b_[ei] = e_[ei] >> 10;
        j_[ei] = e_[ei] & 1023;
        br_[ei] = bhh[j_[ei]];
        bz_[ei] = bhh[Hh + j_[ei]];
        bn_[ei] = bhh[2 * Hh + j_[ei]];
    }

    for (int t = 0; t < Tt; t++) {
        // ---- stage h slice [64 x 128] -> fp16 hi + bf16 lo smem ----
        __syncthreads();
#pragma unroll
        for (int i = 0; i < 8; i++) {
            int f = tid + i * 256;
            int b = f >> 5;
            int c4 = f & 31;
            float4 v = *reinterpret_cast<const float4*>(&hbase[(size_t)b * Hh + k0 + c4 * 4]);
            float hx = __half2float(__float2half_rn(v.x));
            float hy = __half2float(__float2half_rn(v.y));
            float hz = __half2float(__float2half_rn(v.z));
            float hw = __half2float(__float2half_rn(v.w));
            uint32_t* dh = reinterpret_cast<uint32_t*>(sH16) + b * (PRU * 4) + c4 * 2;
            uint32_t* dl = reinterpret_cast<uint32_t*>(sHlb) + b * (PRU * 4) + c4 * 2;
            dh[0] = pk_h2(hx, hy);
            dh[1] = pk_h2(hz, hw);
            dl[0] = pk_bf2(v.x - hx, v.y - hy);
            dl[1] = pk_bf2(v.z - hz, v.w - hw);
        }
        __syncthreads();

        // ---- 2-pass HMMA: gh[b, n] = sum_k h[b,k] * W[n,k] ----
        float acc[2][6][4];
#pragma unroll
        for (int i = 0; i < 2; i++)
#pragma unroll
            for (int j = 0; j < 6; j++)
#pragma unroll
                for (int r = 0; r < 4; r++) acc[i][j][r] = 0.f;

#pragma unroll
        for (int pass = 0; pass < 2; pass++) {
            const uint32_t aBase = pass ? aHlb : aH16;
            const uint32_t bBase = pass ? aWb : aW16;
#pragma unroll
            for (int k16 = 0; k16 < RKC / 16; k16++) {
                uint32_t af[2][4];
#pragma unroll
                for (int mt = 0; mt < 2; mt++) {
                    uint32_t addr = aBase + ((wb + mt * 16 + lrow) * PRU + k16 * 2 + lcol) * 16;
                    LDSM_X4(af[mt][0], af[mt][1], af[mt][2], af[mt][3], addr);
                }
                uint32_t bfr[3][4];
#pragma unroll
                for (int bt = 0; bt < 3; bt++) {
                    uint32_t addr = bBase + ((wn + bt * 16 + lrow) * PRU + k16 * 2 + lcol) * 16;
                    LDSM_X4(bfr[bt][0], bfr[bt][1], bfr[bt][2], bfr[bt][3], addr);
                }
                if (pass == 0) {
#pragma unroll
                    for (int mt = 0; mt < 2; mt++)
#pragma unroll
                        for (int ntl = 0; ntl < 6; ntl++) {
                            int bt = ntl >> 1, lh = ntl & 1;
                            MMA_F16(acc[mt][ntl], af[mt], bfr[bt][lh], bfr[bt][lh + 2]);
                        }
                } else {
#pragma unroll
                    for (int mt = 0; mt < 2; mt++)
#pragma unroll
                        for (int ntl = 0; ntl < 6; ntl++) {
                            int bt = ntl >> 1, lh = ntl & 1;
                            MMA_BF16(acc[mt][ntl], af[mt], bfr[bt][lh], bfr[bt][lh + 2]);
                        }
                }
            }
        }

        // ---- write partials ----
#pragma unroll
        for (int mt = 0; mt < 2; mt++) {
#pragma unroll
            for (int half = 0; half < 2; half++) {
                int b = wb + mt * 16 + er + half * 8;
                size_t rowbase = ((size_t)kt * Bb + b) * G3 + n0g + wn;
#pragma unroll
                for (int ntl = 0; ntl < 6; ntl++) {
                    float2 v;
                    v.x = acc[mt][ntl][half * 2 + 0];
                    v.y = acc[mt][ntl][half * 2 + 1];
                    *reinterpret_cast<float2*>(&g_part[rowbase + ntl * 8 + ec]) = v;
                }
            }
        }

        bar_arrive();   // barrier 1 arrive
        ++gen;

        // prefetch gate inputs (block-private elements; race-free)
        float xr_[2], xz_[2], xn_[2], hold_[2];
#pragma unroll
        for (int ei = 0; ei < 2; ei++) {
            size_t gxb = ((size_t)t * Bb + b_[ei]) * G3;
            xr_[ei] = g_gx[gxb + j_[ei]];
            xz_[ei] = g_gx[gxb + Hh + j_[ei]];
            xn_[ei] = g_gx[gxb + 2 * Hh + j_[ei]];
            hold_[ei] = hbase[e_[ei]];
        }

        bar_wait(bar_base + gen);   // barrier 1 wait (partials visible)

        // ---- fused reduce + gates + state update ----
#pragma unroll
        for (int ei = 0; ei < 2; ei++) {
            int b = b_[ei], j = j_[ei];
            float hr = br_[ei], hz = bz_[ei], hn = bn_[ei];
#pragma unroll
            for (int ks = 0; ks < RKT; ks++) {
                size_t base = ((size_t)ks * Bb + b) * G3;
                hr += g_part[base + j];
                hz += g_part[base + Hh + j];
                hn += g_part[base + 2 * Hh + j];
            }

            float rg = 1.f / (1.f + expf(-(xr_[ei] + hr)));
            float zg = 1.f / (1.f + expf(-(xz_[ei] + hz)));
            float ng = tanhf(xn_[ei] + rg * hn);

            float hnew = (1.f - zg) * ng + zg * hold_[ei];
            g_h[l * Bb * Hh + e_[ei]] = hnew;

            if (l == 0) {
                // fp16/bf16 split of the state feeds layer-1's input GEMM
                size_t arow = ((size_t)t * Bb + b) * Ee + j;
                __half hh = __float2half_rn(hnew);
                float hf = __half2float(hh);
                __nv_bfloat16 lo = __float2bfloat16(hnew - hf);
                g_Ahi[arow] = *reinterpret_cast<uint16_t*>(&hh);
                g_Alo[arow] = *reinterpret_cast<uint16_t*>(&lo);
                dout[HIDS_OFF + ((size_t)b * Tt + t) * Hh + j] = hnew;
            }
        }

        bar_arrive();   // barrier 2
        ++gen;
        bar_wait(bar_base + gen);
    }
}

__global__ void finalize(float* __restrict__ dout) {
    int i = blockIdx.x * blockDim.x + threadIdx.x;
    float h0f = g_h[i];
    float h1f = g_h[Bb * Hh + i];
    dout[OUT_OFF + i] = h1f;
    dout[HID_OFF + i] = h0f;
    dout[HID_OFF + Bb * Hh + i] = h1f;
}

// ---------------------------------------------------------------------------
extern "C" void kernel_launch(void* const* d_in, const int* in_sizes, int n_in,
                              void* d_out, int out_size) {
    const int*   x   = (const int*)d_in[0];
    const float* h0  = (const float*)d_in[1];
    const float* emb = (const float*)d_in[2];
    const float* Wih = (const float*)d_in[3];
    const float* Whh = (const float*)d_in[4];
    const float* bih = (const float*)d_in[5];
    const float* bhh = (const float*)d_in[6];
    float* out = (float*)d_out;

    const int gemm_smem = 4 * GSTG;                          // 73728
    const int rec_smem = (64 + 64 + 192 + 192) * PRU * 16;   // 139264
    cudaFuncSetAttribute(gemm_gx_mma,
                         cudaFuncAttributeMaxDynamicSharedMemorySize, gemm_smem);
    cudaFuncSetAttribute(gru_layer_persist,
                         cudaFuncAttributeMaxDynamicSharedMemorySize, rec_smem);

    init_h<<<(Ll * Bb * Hh + 255) / 256, 256>>>(h0);
    embed_split<<<Tt * Bb, Ee / 4>>>(x, emb);

    dim3 tgrid(G3 / MT_N, (Tt * Bb) / MT_M);    // (24, 256)
    const int nW = (G3 * Ee) / 256;

    // Layer 0
    conv_split_W<<<nW, 256>>>(Wih);
    gemm_gx_mma<<<tgrid, 256, gemm_smem>>>(bih);
    gru_layer_persist<<<RGRID, 256, rec_smem>>>(0, Whh, bhh, out);

    // Layer 1 (A = fp16/bf16 split of layer-0 states, written by the gate phase)
    conv_split_W<<<nW, 256>>>(Wih + (size_t)G3 * Ee);
    gemm_gx_mma<<<tgrid, 256, gemm_smem>>>(bih + G3);
    gru_layer_persist<<<RGRID, 256, rec_smem>>>(1, Whh, bhh, out);

    finalize<<<(Bb * Hh) / 256, 256>>>(out);
}

// round 14
// speedup vs baseline: 2.4041x; 1.0285x over previous
#include <cuda_runtime.h>
#include <cuda_bf16.h>
#include <cuda_fp16.h>
#include <cstdint>

// Problem dims (fixed by the dataset)
#define Vv 32000
#define Ee 1024
#define Hh 1024
#define Ll 2
#define Bb 64
#define Tt 512
#define G3 (3*Hh)

// Output packing: (out [1,B,H]) (hidden [L,B,H]) (hiddens [B,T,H])
#define OUT_OFF  0
#define HID_OFF  (Bb*Hh)
#define HIDS_OFF (Bb*Hh + Ll*Bb*Hh)

// Persistent recurrence partitioning: 128 blocks = 32 n-tiles x 4 k-splits
#define RGRID 128
#define RTN   96             // cols per n-tile (32*96 = 3072)
#define RKT   4              // k-splits
#define RKC   256            // k per split (4*256 = 1024)

// warp-MMA GEMM tiling (input-side)
#define MT_M 128
#define MT_N 128
#define KCH  64
#define NPASS 2              // fp16 hi*hi + bf16 lo*W
#define PADU 9               // uint4 per padded smem row (144B, conflict-free)
#define GSTG 18432           // bytes per A (or B) stage: 128 rows * 144B
#define NSTAGE 3

// recurrence smem row stride: 32 uint4 padded to 33 (528B, odd -> conflict-free)
#define PRU 33

// Scratch (device globals: allocation-free per harness rules)
__device__ float g_gx[(size_t)Tt * Bb * G3];
__device__ float g_part[(size_t)RKT * Bb * G3];
__device__ float g_h[Ll * Bb * Hh];
__device__ uint16_t g_Ahi[(size_t)Tt * Bb * Ee];   // fp16(A)
__device__ uint16_t g_Alo[(size_t)Tt * Bb * Ee];   // bf16(A - fp16(A))
__device__ uint16_t g_Whi[(size_t)G3 * Ee];        // fp16(W)
__device__ uint16_t g_Wbf[(size_t)G3 * Ee];        // bf16(W)

// Grid barrier state (monotonic release counter)
__device__ unsigned g_bar_arrive = 0;
__device__ unsigned g_bar_release = 0;

// ---------------------------------------------------------------------------
// PTX helpers
// ---------------------------------------------------------------------------
__device__ __forceinline__ uint32_t smem_u32(const void* p) {
    uint32_t a;
    asm("{ .reg .u64 t; cvta.to.shared.u64 t, %1; cvt.u32.u64 %0, t; }" : "=r"(a) : "l"(p));
    return a;
}
#define LDSM_X4(r0, r1, r2, r3, a) \
    asm volatile("ldmatrix.sync.aligned.m8n8.x4.shared.b16 {%0,%1,%2,%3}, [%4];" \
                 : "=r"(r0), "=r"(r1), "=r"(r2), "=r"(r3) : "r"(a))
#define MMA_BF16(d, a, b0, b1) \
    asm volatile("mma.sync.aligned.m16n8k16.row.col.f32.bf16.bf16.f32 " \
                 "{%0,%1,%2,%3}, {%4,%5,%6,%7}, {%8,%9}, {%0,%1,%2,%3};" \
                 : "+f"((d)[0]), "+f"((d)[1]), "+f"((d)[2]), "+f"((d)[3]) \
                 : "r"((a)[0]), "r"((a)[1]), "r"((a)[2]), "r"((a)[3]), \
                   "r"(b0), "r"(b1))
#define MMA_F16(d, a, b0, b1) \
    asm volatile("mma.sync.aligned.m16n8k16.row.col.f32.f16.f16.f32 " \
                 "{%0,%1,%2,%3}, {%4,%5,%6,%7}, {%8,%9}, {%0,%1,%2,%3};" \
                 : "+f"((d)[0]), "+f"((d)[1]), "+f"((d)[2]), "+f"((d)[3]) \
                 : "r"((a)[0]), "r"((a)[1]), "r"((a)[2]), "r"((a)[3]), \
                   "r"(b0), "r"(b1))
#define CP_ASYNC16(dst, src) \
    asm volatile("cp.async.cg.shared.global [%0], [%1], 16;" :: "r"(dst), "l"(src) : "memory")
#define CP_COMMIT  asm volatile("cp.async.commit_group;" ::: "memory")
#define CP_WAIT1   asm volatile("cp.async.wait_group 1;" ::: "memory")
#define CP_WAIT0   asm volatile("cp.async.wait_group 0;" ::: "memory")

__device__ __forceinline__ uint32_t pk_bf2(float lo, float hi) {
    __nv_bfloat162 t = __floats2bfloat162_rn(lo, hi);
    return *reinterpret_cast<uint32_t*>(&t);
}
__device__ __forceinline__ uint32_t pk_h2(float lo, float hi) {
    __half2 t = __floats2half2_rn(lo, hi);
    return *reinterpret_cast<uint32_t*>(&t);
}

// Split grid barrier (monotonic counter; base read at kernel start)
__device__ __forceinline__ void bar_arrive() {
    __syncthreads();
    if (threadIdx.x == 0) {
        __threadfence();
        unsigned a = atomicAdd(&g_bar_arrive, 1u);
        if (a == RGRID - 1) {
            g_bar_arrive = 0;
            __threadfence();
            atomicAdd(&g_bar_release, 1u);
        }
    }
}
__device__ __forceinline__ void bar_wait(unsigned target) {
    if (threadIdx.x == 0) {
        while ((int)(*(volatile unsigned*)&g_bar_release - target) < 0) __nanosleep(32);
        __threadfence();
    }
    __syncthreads();
}

// ---------------------------------------------------------------------------
// Embedding with fused fp16/bf16 split
// ---------------------------------------------------------------------------
__global__ void embed_split(const int* __restrict__ x, const float* __restrict__ emb) {
    int row = blockIdx.x;          // t*B + b
    int t = row / Bb;
    int b = row - t * Bb;
    int tok = x[b * Tt + t];
    float4 v = reinterpret_cast<const float4*>(emb + (size_t)tok * Ee)[threadIdx.x];
    float hx = __half2float(__float2half_rn(v.x));
    float hy = __half2float(__float2half_rn(v.y));
    float hz = __half2float(__float2half_rn(v.z));
    float hw = __half2float(__float2half_rn(v.w));
    uint2 wh = make_uint2(pk_h2(hx, hy), pk_h2(hz, hw));
    uint2 wl = make_uint2(pk_bf2(v.x - hx, v.y - hy), pk_bf2(v.z - hz, v.w - hw));
    size_t base = (size_t)row * Ee + threadIdx.x * 4;
    *reinterpret_cast<uint2*>(g_Ahi + base) = wh;
    *reinterpret_cast<uint2*>(g_Alo + base) = wl;
}

__global__ void init_h(const float* __restrict__ h0) {
    int i = blockIdx.x * blockDim.x + threadIdx.x;
    if (i < Ll * Bb * Hh) g_h[i] = h0[i];
}

__global__ void conv_split_W(const float* __restrict__ src) {
    size_t i = (size_t)blockIdx.x * 256 + threadIdx.x;
    float x = src[i];
    __half h = __float2half_rn(x);
    __nv_bfloat16 b = __float2bfloat16(x);
    g_Whi[i] = *reinterpret_cast<uint16_t*>(&h);
    g_Wbf[i] = *reinterpret_cast<uint16_t*>(&b);
}

// ---------------------------------------------------------------------------
// 2-pass split TN GEMM via mma.sync, 3-stage cp.async pipeline.
// g_gx[m,n] = sum_k A[m,k]*W[n,k] + bias[n]; CTA 128x128, 8 warps (2M x 4N).
// Dynamic smem 110592B: A stages @{0,1,2}*GSTG, B stages @3*GSTG+{0,1,2}*GSTG.
// ---------------------------------------------------------------------------
extern __shared__ __align__(16) unsigned char s_raw[];

__global__ __launch_bounds__(256, 2) void gemm_gx_mma(const float* __restrict__ bias) {
    const int tid = threadIdx.x;
    const int wid = tid >> 5, lane = tid & 31;
    const int m0 = blockIdx.y * MT_M;
    const int n0 = blockIdx.x * MT_N;
    const int wm = (wid >> 2) * 64;
    const int wn = (wid & 3) * 32;

    const uint32_t sbase = smem_u32(s_raw);
    const int strow = tid >> 3;
    const int stcol = tid & 7;
    const int lrow = lane & 15;
    const int lcol = lane >> 4;

    float acc[4][4][4];
#pragma unroll
    for (int i = 0; i < 4; i++)
#pragma unroll
        for (int j = 0; j < 4; j++)
#pragma unroll
            for (int r = 0; r < 4; r++) acc[i][j][r] = 0.f;

    auto issue_chunk = [&](int c, int s) {
        int pass = c >> 4, cc = c & 15;
        const uint16_t* Asrc = pass ? g_Alo : g_Ahi;
        const uint16_t* Bsrc = pass ? g_Wbf : g_Whi;
#pragma unroll
        for (int i = 0; i < 4; i++) {
            int r = strow + 32 * i;
            const uint16_t* ga = Asrc + (size_t)(m0 + r) * Ee + cc * KCH + stcol * 8;
            const uint16_t* gb = Bsrc + (size_t)(n0 + r) * Ee + cc * KCH + stcol * 8;
            uint32_t off = (uint32_t)(r * PADU + stcol) * 16 + s * GSTG;
            CP_ASYNC16(sbase + off, ga);
            CP_ASYNC16(sbase + NSTAGE * GSTG + off, gb);
        }
    };

    issue_chunk(0, 0);
    CP_COMMIT;
    issue_chunk(1, 1);
    CP_COMMIT;

    const int NCH = NPASS * 16;      // 32
    for (int c = 0; c < NCH; c++) {
        if (c < NCH - 2) CP_WAIT1; else CP_WAIT0;
        __syncthreads();
        if (c < NCH - 2) {
            issue_chunk(c + 2, (c + 2) % NSTAGE);
            CP_COMMIT;
        }

        const uint32_t sa = sbase + (c % NSTAGE) * GSTG;
        const uint32_t sb = sbase + NSTAGE * GSTG + (c % NSTAGE) * GSTG;
#pragma unroll
        for (int k16 = 0; k16 < KCH / 16; k16++) {
            uint32_t af[4][4];
#pragma unroll
            for (int mt = 0; mt < 4; mt++) {
                uint32_t addr = sa + ((wm + mt * 16 + lrow) * PADU + k16 * 2 + lcol) * 16;
                LDSM_X4(af[mt][0], af[mt][1], af[mt][2], af[mt][3], addr);
            }
            uint32_t bf[2][4];
#pragma unroll
            for (int bt = 0; bt < 2; bt++) {
                uint32_t addr = sb + ((wn + bt * 16 + lrow) * PADU + k16 * 2 + lcol) * 16;
                LDSM_X4(bf[bt][0], bf[bt][1], bf[bt][2], bf[bt][3], addr);
            }
            if (c < 16) {
#pragma unroll
                for (int mt = 0; mt < 4; mt++)
#pragma unroll
                    for (int nt = 0; nt < 4; nt++) {
                        int bt = nt >> 1, lh = nt & 1;
                        MMA_F16(acc[mt][nt], af[mt], bf[bt][lh], bf[bt][lh + 2]);
                    }
            } else {
#pragma unroll
                for (int mt = 0; mt < 4; mt++)
#pragma unroll
                    for (int nt = 0; nt < 4; nt++) {
                        int bt = nt >> 1, lh = nt & 1;
                        MMA_BF16(acc[mt][nt], af[mt], bf[bt][lh], bf[bt][lh + 2]);
                    }
            }
        }
    }

    // Epilogue: fragment layout -> gmem with bias
    const int er = lane >> 2;
    const int ec = (lane & 3) * 2;
#pragma unroll
    for (int mt = 0; mt < 4; mt++) {
#pragma unroll
        for (int half = 0; half < 2; half++) {
            int grow = m0 + wm + mt * 16 + er + half * 8;
            size_t base = (size_t)grow * G3;
#pragma unroll
            for (int nt = 0; nt < 4; nt++) {
                int gcol = n0 + wn + nt * 8 + ec;
                float2 v;
                v.x = acc[mt][nt][half * 2 + 0] + bias[gcol];
                v.y = acc[mt][nt][half * 2 + 1] + bias[gcol + 1];
                *reinterpret_cast<float2*>(&g_gx[base + gcol]) = v;
            }
        }
    }
}

// ---------------------------------------------------------------------------
// Persistent recurrence kernel: 2-pass HMMA, 4-way k-split, 96-col n-tiles.
// Block (kt = bid>>5, nt = bid&31). Smem 168960B:
//   sH16/sHlb [64 x 33u4], sW16/sWb [96 x 33u4]
// Warps: 4(b) x 2(n): wb = (wid>>1)*16, wn = (wid&1)*48.
// ---------------------------------------------------------------------------
__global__ __launch_bounds__(256, 1) void gru_layer_persist(
    int l, const float* __restrict__ Whh_all, const float* __restrict__ bhh_all,
    float* __restrict__ dout) {

    uint4* s4 = reinterpret_cast<uint4*>(s_raw);
    uint16_t* sH16 = reinterpret_cast<uint16_t*>(s4 + 0);       // 64*33 u4
    uint16_t* sHlb = reinterpret_cast<uint16_t*>(s4 + 2112);    // 64*33 u4
    uint16_t* sW16 = reinterpret_cast<uint16_t*>(s4 + 4224);    // 96*33 u4
    uint16_t* sWb  = reinterpret_cast<uint16_t*>(s4 + 7392);    // 96*33 u4

    const int tid = threadIdx.x;
    const int bid = blockIdx.x;
    const int wid = tid >> 5, lane = tid & 31;
    const int nt = bid & 31;
    const int kt = bid >> 5;
    const int n0g = nt * RTN;
    const int k0 = kt * RKC;

    const float* W = Whh_all + (size_t)l * G3 * Hh;
    const float* bhh = bhh_all + l * G3;
    const float* hbase = g_h + l * Bb * Hh;

    __shared__ unsigned s_base0;
    if (tid == 0) s_base0 = *(volatile unsigned*)&g_bar_release;

    // ---- startup: W slice [96 x 256] -> fp16 + bf16 in smem ----
    for (int f = tid; f < RTN * 64; f += 256) {
        int r = f >> 6;          // 0..95
        int c4 = f & 63;         // float4 col 0..63
        float4 v = *reinterpret_cast<const float4*>(&W[(size_t)(n0g + r) * Hh + k0 + c4 * 4]);
        uint32_t* dh = reinterpret_cast<uint32_t*>(sW16) + r * (PRU * 4) + c4 * 2;
        uint32_t* db = reinterpret_cast<uint32_t*>(sWb)  + r * (PRU * 4) + c4 * 2;
        dh[0] = pk_h2(v.x, v.y);
        dh[1] = pk_h2(v.z, v.w);
        db[0] = pk_bf2(v.x, v.y);
        db[1] = pk_bf2(v.z, v.w);
    }
    __syncthreads();
    const unsigned bar_base = s_base0;
    unsigned gen = 0;

    const uint32_t aH16 = smem_u32(sH16), aHlb = smem_u32(sHlb);
    const uint32_t aW16 = smem_u32(sW16), aWb = smem_u32(sWb);

    const int wb = (wid >> 1) * 16;    // batch base: 0,16,32,48
    const int wn = (wid & 1) * 48;     // col base within tile: 0,48
    const int lrow = lane & 15;
    const int lcol = lane >> 4;
    const int er = lane >> 2;
    const int ec = (lane & 3) * 2;

    // gate-phase constants
    int e_[2], b_[2], j_[2];
    float br_[2], bz_[2], bn_[2];
#pragma unroll
    for (int ei = 0; ei < 2; ei++) {
        e_[ei] = bid * 512 + ei * 256 + tid;
        b_[ei] = e_[ei] >> 10;
        j_[ei] = e_[ei] & 1023;
        br_[ei] = bhh[j_[ei]];
        bz_[ei] = bhh[Hh + j_[ei]];
        bn_[ei] = bhh[2 * Hh + j_[ei]];
    }

    for (int t = 0; t < Tt; t++) {
        // ---- stage h slice [64 x 256] -> fp16 hi + bf16 lo smem ----
        __syncthreads();
#pragma unroll
        for (int i = 0; i < 16; i++) {
            int f = tid + i * 256;
            int b = f >> 6;          // 0..63
            int c4 = f & 63;
            float4 v = *reinterpret_cast<const float4*>(&hbase[(size_t)b * Hh + k0 + c4 * 4]);
            float hx = __half2float(__float2half_rn(v.x));
            float hy = __half2float(__float2half_rn(v.y));
            float hz = __half2float(__float2half_rn(v.z));
            float hw = __half2float(__float2half_rn(v.w));
            uint32_t* dh = reinterpret_cast<uint32_t*>(sH16) + b * (PRU * 4) + c4 * 2;
            uint32_t* dl = reinterpret_cast<uint32_t*>(sHlb) + b * (PRU * 4) + c4 * 2;
            dh[0] = pk_h2(hx, hy);
            dh[1] = pk_h2(hz, hw);
            dl[0] = pk_bf2(v.x - hx, v.y - hy);
            dl[1] = pk_bf2(v.z - hz, v.w - hw);
        }
        __syncthreads();

        // ---- 2-pass HMMA: gh[b, n] = sum_k h[b,k] * W[n,k] ----
        float acc[6][4];
#pragma unroll
        for (int j = 0; j < 6; j++)
#pragma unroll
            for (int r = 0; r < 4; r++) acc[j][r] = 0.f;

#pragma unroll
        for (int pass = 0; pass < 2; pass++) {
            const uint32_t aBase = pass ? aHlb : aH16;
            const uint32_t bBase = pass ? aWb : aW16;
#pragma unroll
            for (int k16 = 0; k16 < RKC / 16; k16++) {
                uint32_t af[4];
                {
                    uint32_t addr = aBase + ((wb + lrow) * PRU + k16 * 2 + lcol) * 16;
                    LDSM_X4(af[0], af[1], af[2], af[3], addr);
                }
                uint32_t bfr[3][4];
#pragma unroll
                for (int bt = 0; bt < 3; bt++) {
                    uint32_t addr = bBase + ((wn + bt * 16 + lrow) * PRU + k16 * 2 + lcol) * 16;
                    LDSM_X4(bfr[bt][0], bfr[bt][1], bfr[bt][2], bfr[bt][3], addr);
                }
                if (pass == 0) {
#pragma unroll
                    for (int ntl = 0; ntl < 6; ntl++) {
                        int bt = ntl >> 1, lh = ntl & 1;
                        MMA_F16(acc[ntl], af, bfr[bt][lh], bfr[bt][lh + 2]);
                    }
                } else {
#pragma unroll
                    for (int ntl = 0; ntl < 6; ntl++) {
                        int bt = ntl >> 1, lh = ntl & 1;
                        MMA_BF16(acc[ntl], af, bfr[bt][lh], bfr[bt][lh + 2]);
                    }
                }
            }
        }

        // ---- write partials: g_part[kt][b][n0g + wn + ntl*8 + ec] ----
#pragma unroll
        for (int half = 0; half < 2; half++) {
            int b = wb + er + half * 8;
            size_t rowbase = ((size_t)kt * Bb + b) * G3 + n0g + wn;
#pragma unroll
            for (int ntl = 0; ntl < 6; ntl++) {
                float2 v;
                v.x = acc[ntl][half * 2 + 0];
                v.y = acc[ntl][half * 2 + 1];
                *reinterpret_cast<float2*>(&g_part[rowbase + ntl * 8 + ec]) = v;
            }
        }

        bar_arrive();   // barrier 1 arrive
        ++gen;

        // prefetch gate inputs (block-private elements; race-free)
        float xr_[2], xz_[2], xn_[2], hold_[2];
#pragma unroll
        for (int ei = 0; ei < 2; ei++) {
            size_t gxb = ((size_t)t * Bb + b_[ei]) * G3;
            xr_[ei] = g_gx[gxb + j_[ei]];
            xz_[ei] = g_gx[gxb + Hh + j_[ei]];
            xn_[ei] = g_gx[gxb + 2 * Hh + j_[ei]];
            hold_[ei] = hbase[e_[ei]];
        }

        bar_wait(bar_base + gen);   // barrier 1 wait (partials visible)

        // ---- fused reduce + gates + state update ----
#pragma unroll
        for (int ei = 0; ei < 2; ei++) {
            int b = b_[ei], j = j_[ei];
            float hr = br_[ei], hz = bz_[ei], hn = bn_[ei];
#pragma unroll
            for (int ks = 0; ks < RKT; ks++) {
                size_t base = ((size_t)ks * Bb + b) * G3;
                hr += g_part[base + j];
                hz += g_part[base + Hh + j];
                hn += g_part[base + 2 * Hh + j];
            }

            float rg = 1.f / (1.f + expf(-(xr_[ei] + hr)));
            float zg = 1.f / (1.f + expf(-(xz_[ei] + hz)));
            float ng = tanhf(xn_[ei] + rg * hn);

            float hnew = (1.f - zg) * ng + zg * hold_[ei];
            g_h[l * Bb * Hh + e_[ei]] = hnew;

            if (l == 0) {
                // fp16/bf16 split of the state feeds layer-1's input GEMM
                size_t arow = ((size_t)t * Bb + b) * Ee + j;
                __half hh = __float2half_rn(hnew);
                float hf = __half2float(hh);
                __nv_bfloat16 lo = __float2bfloat16(hnew - hf);
                g_Ahi[arow] = *reinterpret_cast<uint16_t*>(&hh);
                g_Alo[arow] = *reinterpret_cast<uint16_t*>(&lo);
                dout[HIDS_OFF + ((size_t)b * Tt + t) * Hh + j] = hnew;
            }
        }

        bar_arrive();   // barrier 2
        ++gen;
        bar_wait(bar_base + gen);
    }
}

__global__ void finalize(float* __restrict__ dout) {
    int i = blockIdx.x * blockDim.x + threadIdx.x;
    float h0f = g_h[i];
    float h1f = g_h[Bb * Hh + i];
    dout[OUT_OFF + i] = h1f;
    dout[HID_OFF + i] = h0f;
    dout[HID_OFF + Bb * Hh + i] = h1f;
}

// ---------------------------------------------------------------------------
extern "C" void kernel_launch(void* const* d_in, const int* in_sizes, int n_in,
                              void* d_out, int out_size) {
    const int*   x   = (const int*)d_in[0];
    const float* h0  = (const float*)d_in[1];
    const float* emb = (const float*)d_in[2];
    const float* Wih = (const float*)d_in[3];
    const float* Whh = (const float*)d_in[4];
    const float* bih = (const float*)d_in[5];
    const float* bhh = (const float*)d_in[6];
    float* out = (float*)d_out;

    const int gemm_smem = 2 * NSTAGE * GSTG;                    // 110592
    const int rec_smem = (64 + 64 + 96 + 96) * PRU * 16;        // 168960
    cudaFuncSetAttribute(gemm_gx_mma,
                         cudaFuncAttributeMaxDynamicSharedMemorySize, gemm_smem);
    cudaFuncSetAttribute(gru_layer_persist,
                         cudaFuncAttributeMaxDynamicSharedMemorySize, rec_smem);

    init_h<<<(Ll * Bb * Hh + 255) / 256, 256>>>(h0);
    embed_split<<<Tt * Bb, Ee / 4>>>(x, emb);

    dim3 tgrid(G3 / MT_N, (Tt * Bb) / MT_M);    // (24, 256)
    const int nW = (G3 * Ee) / 256;

    // Layer 0
    conv_split_W<<<nW, 256>>>(Wih);
    gemm_gx_mma<<<tgrid, 256, gemm_smem>>>(bih);
    gru_layer_persist<<<RGRID, 256, rec_smem>>>(0, Whh, bhh, out);

    // Layer 1 (A = fp16/bf16 split of layer-0 states, written by the gate phase)
    conv_split_W<<<nW, 256>>>(Wih + (size_t)G3 * Ee);
    gemm_gx_mma<<<tgrid, 256, gemm_smem>>>(bih + G3);
    gru_layer_persist<<<RGRID, 256, rec_smem>>>(1, Whh, bhh, out);

    finalize<<<(Bb * Hh) / 256, 256>>>(out);
}